// round 4
// baseline (speedup 1.0000x reference)
#include <cuda_runtime.h>
#include <mma.h>
#include <cstdint>
#include <cstddef>

using namespace nvcuda;

#define BATCH  2
#define SEQ    2048
#define DMODEL 1024
#define NHEAD  16
#define DHEAD  64
#define BH     (BATCH*NHEAD)
#define MROWS  (BATCH*SEQ)      // 4096
#define SCALE  0.022097086912079608f  // 1/sqrt(2048)

// ---------------- scratch (device globals; allocation-free rule) -----------
__device__ __align__(16) float g_Xq[(size_t)MROWS * DMODEL];
__device__ __align__(16) float g_Xk[(size_t)MROWS * DMODEL];
__device__ __align__(16) float g_Xv[(size_t)MROWS * DMODEL];
__device__ __align__(16) float g_Wq[(size_t)NHEAD * DMODEL * DHEAD];
__device__ __align__(16) float g_Wk[(size_t)NHEAD * DMODEL * DHEAD];
__device__ __align__(16) float g_Wv[(size_t)NHEAD * DMODEL * DHEAD];
__device__ __align__(16) float g_WOr[(size_t)DMODEL * DMODEL];
__device__ __align__(16) float g_Q[(size_t)BH * SEQ * DHEAD];
__device__ __align__(16) float g_K[(size_t)BH * SEQ * DHEAD];
__device__ __align__(16) float g_V[(size_t)BH * SEQ * DHEAD];   // scaled in-place by den
__device__ __align__(16) float g_P[(size_t)BH * SEQ * SEQ];
__device__ __align__(16) float g_Ocat[(size_t)MROWS * DMODEL];

typedef wmma::fragment<wmma::matrix_a, 16, 16, 8, wmma::precision::tf32, wmma::row_major> FragA;
typedef wmma::fragment<wmma::matrix_b, 16, 16, 8, wmma::precision::tf32, wmma::row_major> FragB;
typedef wmma::fragment<wmma::matrix_b, 16, 16, 8, wmma::precision::tf32, wmma::col_major> FragBt;
typedef wmma::fragment<wmma::accumulator, 16, 16, 8, float> FragC;

__device__ __forceinline__ float rtf(float x) { return wmma::__float_to_tf32(x); }
__device__ __forceinline__ float4 rtf4(float4 v) {
    v.x = rtf(v.x); v.y = rtf(v.y); v.z = rtf(v.z); v.w = rtf(v.w);
    return v;
}

__device__ __forceinline__ void cp16(void* smem, const void* gmem) {
    uint32_t s = (uint32_t)__cvta_generic_to_shared(smem);
    asm volatile("cp.async.cg.shared.global [%0], [%1], 16;" :: "r"(s), "l"(gmem));
}
__device__ __forceinline__ void cp_commit() { asm volatile("cp.async.commit_group;"); }
template <int N> __device__ __forceinline__ void cp_wait() {
    asm volatile("cp.async.wait_group %0;" :: "n"(N));
    }

// ---------------------------------------------------------------------------
// Prologue: round fp32 -> tf32 copies so all GEMMs can use raw cp.async.
// ---------------------------------------------------------------------------
__global__ __launch_bounds__(256) void round_kernel(const float4* __restrict__ src,
                                                    float4* __restrict__ dst, int n4) {
    int i = blockIdx.x * 256 + threadIdx.x;
    if (i < n4) dst[i] = rtf4(src[i]);
}

// ---------------------------------------------------------------------------
// Unified 128x128-tile GEMM, double-buffered BK=32.
// MODE 0/1/2: per-head projections (B = W[h][k][e], epilogue -> g_Q/g_K/g_V head-major)
// MODE 3:     output projection   (B = g_WOr,      epilogue -> C fp32)
// ---------------------------------------------------------------------------
template <int MODE>
__global__ __launch_bounds__(256, 2) void gemm_kernel(float* __restrict__ C) {
    const float* A = (MODE == 0) ? g_Xq : (MODE == 1) ? g_Xk : (MODE == 2) ? g_Xv : g_Ocat;
    const float* B = (MODE == 0) ? g_Wq : (MODE == 1) ? g_Wk : (MODE == 2) ? g_Wv : g_WOr;

    extern __shared__ float sm[];
    float* As = sm;                 // [2][128][40]
    float* Bs = sm + 2 * 128 * 40;  // [2][32][136]

    int mt = blockIdx.x, nt = blockIdx.y;
    int t = threadIdx.x, wid = t >> 5;
    int wm = wid >> 1, wn = wid & 1;   // 4x2 warps -> 128x128, warp 32x64
    int m0 = mt * 128;

    FragC acc[2][4];
#pragma unroll
    for (int i = 0; i < 2; i++)
#pragma unroll
        for (int j = 0; j < 4; j++) wmma::fill_fragment(acc[i][j], 0.0f);

    auto issue = [&](int kk, int buf) {
        float* Ab = As + buf * (128 * 40);
        float* Bb = Bs + buf * (32 * 136);
#pragma unroll
        for (int j = 0; j < 4; j++) {
            int i = t + j * 256;
            int row = i >> 3, col = (i & 7) << 2;
            cp16(&Ab[row * 40 + col], &A[(size_t)(m0 + row) * DMODEL + kk + col]);
        }
#pragma unroll
        for (int j = 0; j < 4; j++) {
            int i = t + j * 256;
            int row = i >> 5, col = (i & 31) << 2;
            const float* src;
            if (MODE == 3) {
                src = &B[(size_t)(kk + row) * DMODEL + nt * 128 + col];
            } else {
                int h = nt * 2 + (col >> 6), e = col & 63;
                src = &B[((size_t)h * DMODEL + kk + row) * DHEAD + e];
            }
            cp16(&Bb[row * 136 + col], src);
        }
    };

    issue(0, 0); cp_commit();
#pragma unroll 1
    for (int it = 0; it < 32; it++) {
        if (it < 31) { issue((it + 1) * 32, (it + 1) & 1); cp_commit(); cp_wait<1>(); }
        else cp_wait<0>();
        __syncthreads();
        float* Ab = As + (it & 1) * (128 * 40);
        float* Bb = Bs + (it & 1) * (32 * 136);
#pragma unroll
        for (int ks = 0; ks < 32; ks += 8) {
            FragA a[2]; FragB bfr[4];
#pragma unroll
            for (int i = 0; i < 2; i++)
                wmma::load_matrix_sync(a[i], &Ab[(wm * 32 + i * 16) * 40 + ks], 40);
#pragma unroll
            for (int j = 0; j < 4; j++)
                wmma::load_matrix_sync(bfr[j], &Bb[ks * 136 + wn * 64 + j * 16], 136);
#pragma unroll
            for (int i = 0; i < 2; i++)
#pragma unroll
                for (int j = 0; j < 4; j++)
                    wmma::mma_sync(acc[i][j], a[i], bfr[j], acc[i][j]);
        }
        __syncthreads();
    }

    if (MODE == 3) {
#pragma unroll
        for (int i = 0; i < 2; i++)
#pragma unroll
            for (int j = 0; j < 4; j++)
                wmma::store_matrix_sync(
                    &C[(size_t)(m0 + wm * 32 + i * 16) * DMODEL + nt * 128 + wn * 64 + j * 16],
                    acc[i][j], DMODEL, wmma::mem_row_major);
    } else {
        float* Outp = (MODE == 0) ? g_Q : (MODE == 1) ? g_K : g_V;
        int b = m0 >> 11, srow = m0 & (SEQ - 1);
        int h = nt * 2 + wn;
        float* Ob = Outp + ((size_t)(b * NHEAD + h) * SEQ + srow) * DHEAD;
#pragma unroll
        for (int i = 0; i < 2; i++)
#pragma unroll
            for (int j = 0; j < 4; j++) {
#pragma unroll
                for (int e = 0; e < acc[i][j].num_elements; e++)
                    acc[i][j].x[e] = rtf(acc[i][j].x[e]);
                wmma::store_matrix_sync(&Ob[(size_t)(wm * 32 + i * 16) * DHEAD + j * 16],
                                        acc[i][j], DHEAD, wmma::mem_row_major);
            }
    }
}

// ---------------------------------------------------------------------------
// den_kernel: per (64-wide k-stripe, bh):
//   scores via wmma (Q double-buffered cp.async), exp -> g_P (rounded), column
//   sums -> 1/den, then scales g_V rows in place.
// qt0 = (kt>>2)*2 extends coverage so pv's 256-row tiles read only defined P.
// ---------------------------------------------------------------------------
__global__ __launch_bounds__(256, 2) void den_kernel() {
    int kt = gridDim.x - 1 - blockIdx.x;  // long stripes first
    int bh = blockIdx.y;

    extern __shared__ float sm[];
    float* Ks = sm;             // [64][72]
    float* Qs = sm + 64 * 72;   // [2][128][72]  (consumed buf reused for scores)
    __shared__ float red[256];
    __shared__ float invs[64];

    int t = threadIdx.x, wid = t >> 5;
    int wm = wid >> 1, wn = wid & 1;  // 4x2 -> 128x64, warp 32x32

    const float* Qb = g_Q + (size_t)bh * SEQ * DHEAD;
    const float* Kb = g_K + ((size_t)bh * SEQ + kt * 64) * DHEAD;
    float* Pb = g_P + (size_t)bh * SEQ * SEQ + kt * 64;

    int qt0 = (kt >> 2) << 1;
    int nq = SEQ / 128 - qt0;

    auto issueQ = [&](int qt, int buf) {
        float* Qd = Qs + buf * (128 * 72);
#pragma unroll
        for (int j = 0; j < 8; j++) {
            int i = t + j * 256;
            int row = i >> 4, c4 = (i & 15) << 2;
            cp16(&Qd[row * 72 + c4], &Qb[(size_t)(qt * 128 + row) * DHEAD + c4]);
        }
    };

    // prologue: K stripe + first Q tile in one group
#pragma unroll
    for (int j = 0; j < 4; j++) {
        int i = t + j * 256;
        int row = i >> 4, c4 = (i & 15) << 2;
        cp16(&Ks[row * 72 + c4], &Kb[(size_t)row * DHEAD + c4]);
    }
    issueQ(qt0, 0); cp_commit();

    int col = t & 63, ro = t >> 6;
    int k = kt * 64 + col;
    float part = 0.0f;

#pragma unroll 1
    for (int it = 0; it < nq; it++) {
        int qt = qt0 + it;
        if (it + 1 < nq) { issueQ(qt + 1, (it + 1) & 1); cp_commit(); cp_wait<1>(); }
        else cp_wait<0>();
        __syncthreads();

        float* Qt = Qs + (it & 1) * (128 * 72);
        FragC cf[2][2];
#pragma unroll
        for (int i = 0; i < 2; i++)
#pragma unroll
            for (int j = 0; j < 2; j++) wmma::fill_fragment(cf[i][j], 0.0f);

#pragma unroll
        for (int ks = 0; ks < 64; ks += 8) {
            FragA a[2]; FragBt btf[2];
#pragma unroll
            for (int i = 0; i < 2; i++)
                wmma::load_matrix_sync(a[i], &Qt[(wm * 32 + i * 16) * 72 + ks], 72);
#pragma unroll
            for (int j = 0; j < 2; j++)
                wmma::load_matrix_sync(btf[j], &Ks[(wn * 32 + j * 16) * 72 + ks], 72);
#pragma unroll
            for (int i = 0; i < 2; i++)
#pragma unroll
                for (int j = 0; j < 2; j++)
                    wmma::mma_sync(cf[i][j], a[i], btf[j], cf[i][j]);
        }
        __syncthreads();  // all warps done reading Qt -> overlay scores
#pragma unroll
        for (int i = 0; i < 2; i++)
#pragma unroll
            for (int j = 0; j < 2; j++)
                wmma::store_matrix_sync(&Qt[(wm * 32 + i * 16) * 72 + wn * 32 + j * 16],
                                        cf[i][j], 72, wmma::mem_row_major);
        __syncthreads();

        int q0 = qt * 128;
#pragma unroll
        for (int i = 0; i < 32; i++) {
            int row = ro + i * 4;
            int q = q0 + row;
            float s = Qt[row * 72 + col];
            float v = (k <= q) ? __expf((s + (float)(k - q)) * SCALE) : 0.0f;
            part += v;
            Pb[(size_t)q * SEQ + col] = rtf(v);
        }
        __syncthreads();
    }

    red[t] = part;
    __syncthreads();
    if (t < 64) {
        float tot = red[t] + red[t + 64] + red[t + 128] + red[t + 192];
        invs[t] = 1.0f / tot;
    }
    __syncthreads();

    // scale V rows [kt*64, kt*64+64) in place (rounded)
    float4* Vb4 = (float4*)(g_V + ((size_t)bh * SEQ + kt * 64) * DHEAD);
#pragma unroll
    for (int j = 0; j < 4; j++) {
        int i = t + j * 256;
        int row = i >> 4, c4 = i & 15;
        float iv = invs[row];
        float4 v = Vb4[row * 16 + c4];
        v.x = rtf(v.x * iv); v.y = rtf(v.y * iv);
        v.z = rtf(v.z * iv); v.w = rtf(v.w * iv);
        Vb4[row * 16 + c4] = v;
    }
}

// ---------------------------------------------------------------------------
// pv_kernel: Ocat tile [256 q][64 e] = P[q, 0..(qt+1)*256) @ V'  (V' pre-scaled)
// cp.async double-buffered BK=32; warp tile 64x32 (8 mma chains).
// ---------------------------------------------------------------------------
__global__ __launch_bounds__(256, 2) void pv_kernel() {
    int qt = gridDim.x - 1 - blockIdx.x;  // heavy first
    int bh = blockIdx.y;
    int b = bh >> 4, h = bh & 15;

    extern __shared__ float sm[];
    float* Ps = sm;                  // [2][256][40]
    float* Vs = sm + 2 * 256 * 40;   // [2][32][72]

    int t = threadIdx.x, wid = t >> 5;
    int wm = wid >> 1, wn = wid & 1;  // 4x2 -> 256x64, warp 64x32

    const float* Prow = g_P + ((size_t)bh * SEQ + qt * 256) * SEQ;
    const float* Vb = g_V + (size_t)bh * SEQ * DHEAD;

    FragC acc[4][2];
#pragma unroll
    for (int i = 0; i < 4; i++)
#pragma unroll
        for (int j = 0; j < 2; j++) wmma::fill_fragment(acc[i][j], 0.0f);

    int niter = (qt + 1) * 8;

    auto issue = [&](int ki, int buf) {
        float* Pd = Ps + buf * (256 * 40);
        float* Vd = Vs + buf * (32 * 72);
#pragma unroll
        for (int j = 0; j < 8; j++) {
            int i = t + j * 256;
            int row = i >> 3, c4 = (i & 7) << 2;
            cp16(&Pd[row * 40 + c4], &Prow[(size_t)row * SEQ + ki * 32 + c4]);
        }
#pragma unroll
        for (int j = 0; j < 2; j++) {
            int i = t + j * 256;
            int row = i >> 4, c4 = (i & 15) << 2;
            cp16(&Vd[row * 72 + c4], &Vb[(size_t)(ki * 32 + row) * DHEAD + c4]);
        }
    };

    issue(0, 0); cp_commit();
#pragma unroll 1
    for (int it = 0; it < niter; it++) {
        if (it + 1 < niter) { issue(it + 1, (it + 1) & 1); cp_commit(); cp_wait<1>(); }
        else cp_wait<0>();
        __syncthreads();
        float* Pt = Ps + (it & 1) * (256 * 40);
        float* Vt = Vs + (it & 1) * (32 * 72);
#pragma unroll
        for (int ks = 0; ks < 32; ks += 8) {
            FragA a[4]; FragB bfr[2];
#pragma unroll
            for (int i = 0; i < 4; i++)
                wmma::load_matrix_sync(a[i], &Pt[(wm * 64 + i * 16) * 40 + ks], 40);
#pragma unroll
            for (int j = 0; j < 2; j++)
                wmma::load_matrix_sync(bfr[j], &Vt[ks * 72 + wn * 32 + j * 16], 72);
#pragma unroll
            for (int i = 0; i < 4; i++)
#pragma unroll
                for (int j = 0; j < 2; j++)
                    wmma::mma_sync(acc[i][j], a[i], bfr[j], acc[i][j]);
        }
        __syncthreads();
    }

    float* Ob = g_Ocat + ((size_t)(b * SEQ + qt * 256)) * DMODEL + h * DHEAD;
#pragma unroll
    for (int i = 0; i < 4; i++)
#pragma unroll
        for (int j = 0; j < 2; j++) {
#pragma unroll
            for (int e = 0; e < acc[i][j].num_elements; e++)
                acc[i][j].x[e] = rtf(acc[i][j].x[e]);
            wmma::store_matrix_sync(&Ob[(size_t)(wm * 64 + i * 16) * DMODEL + wn * 32 + j * 16],
                                    acc[i][j], DMODEL, wmma::mem_row_major);
        }
}

// ---------------------------------------------------------------------------
// Launch. Inputs: keys, queries, values, WQ, WK, WV, WO, masking
// ---------------------------------------------------------------------------
extern "C" void kernel_launch(void* const* d_in, const int* in_sizes, int n_in,
                              void* d_out, int out_size) {
    const float* keys    = (const float*)d_in[0];
    const float* queries = (const float*)d_in[1];
    const float* values  = (const float*)d_in[2];
    const float* WQ      = (const float*)d_in[3];
    const float* WK      = (const float*)d_in[4];
    const float* WV      = (const float*)d_in[5];
    const float* WO      = (const float*)d_in[6];
    float* out = (float*)d_out;
    (void)in_sizes; (void)n_in; (void)out_size;

    const int gemmSmem = 2 * 128 * 40 * 4 + 2 * 32 * 136 * 4;   // 75776
    const int denSmem  = (64 * 72 + 2 * 128 * 72) * 4;          // 92160
    const int pvSmem   = (2 * 256 * 40 + 2 * 32 * 72) * 4;      // 100352
    cudaFuncSetAttribute(gemm_kernel<0>, cudaFuncAttributeMaxDynamicSharedMemorySize, gemmSmem);
    cudaFuncSetAttribute(gemm_kernel<1>, cudaFuncAttributeMaxDynamicSharedMemorySize, gemmSmem);
    cudaFuncSetAttribute(gemm_kernel<2>, cudaFuncAttributeMaxDynamicSharedMemorySize, gemmSmem);
    cudaFuncSetAttribute(gemm_kernel<3>, cudaFuncAttributeMaxDynamicSharedMemorySize, gemmSmem);
    cudaFuncSetAttribute(den_kernel,     cudaFuncAttributeMaxDynamicSharedMemorySize, denSmem);
    cudaFuncSetAttribute(pv_kernel,      cudaFuncAttributeMaxDynamicSharedMemorySize, pvSmem);

    float* xq; float* xk; float* xv; float* wq; float* wk; float* wv; float* wo;
    cudaGetSymbolAddress((void**)&xq, g_Xq);
    cudaGetSymbolAddress((void**)&xk, g_Xk);
    cudaGetSymbolAddress((void**)&xv, g_Xv);
    cudaGetSymbolAddress((void**)&wq, g_Wq);
    cudaGetSymbolAddress((void**)&wk, g_Wk);
    cudaGetSymbolAddress((void**)&wv, g_Wv);
    cudaGetSymbolAddress((void**)&wo, g_WOr);

    const int nX4 = MROWS * DMODEL / 4;           // 1048576
    const int nW4 = NHEAD * DMODEL * DHEAD / 4;   // 262144
    const int nO4 = DMODEL * DMODEL / 4;          // 262144
    round_kernel<<<nX4 / 256, 256>>>((const float4*)queries, (float4*)xq, nX4);
    round_kernel<<<nX4 / 256, 256>>>((const float4*)keys,    (float4*)xk, nX4);
    round_kernel<<<nX4 / 256, 256>>>((const float4*)values,  (float4*)xv, nX4);
    round_kernel<<<nW4 / 256, 256>>>((const float4*)WQ, (float4*)wq, nW4);
    round_kernel<<<nW4 / 256, 256>>>((const float4*)WK, (float4*)wk, nW4);
    round_kernel<<<nW4 / 256, 256>>>((const float4*)WV, (float4*)wv, nW4);
    round_kernel<<<nO4 / 256, 256>>>((const float4*)WO, (float4*)wo, nO4);

    gemm_kernel<0><<<dim3(MROWS / 128, 8), 256, gemmSmem>>>(nullptr);
    gemm_kernel<1><<<dim3(MROWS / 128, 8), 256, gemmSmem>>>(nullptr);
    gemm_kernel<2><<<dim3(MROWS / 128, 8), 256, gemmSmem>>>(nullptr);

    den_kernel<<<dim3(SEQ / 64, BH), 256, denSmem>>>();
    pv_kernel<<<dim3(SEQ / 256, BH), 256, pvSmem>>>();

    gemm_kernel<3><<<dim3(MROWS / 128, 8), 256, gemmSmem>>>(out);
}

// round 6
// speedup vs baseline: 2.2896x; 2.2896x over previous
#include <cuda_runtime.h>
#include <cstdint>
#include <cstddef>

#define BATCH  2
#define SEQ    2048
#define DMODEL 1024
#define NHEAD  16
#define DHEAD  64
#define BH     (BATCH*NHEAD)
#define MROWS  (BATCH*SEQ)
#define SCALE  0.022097086912079608f   // 1/sqrt(2048)

// ---------------- scratch (device globals; allocation-free rule) -----------
__device__ __align__(16) float g_Xr[(size_t)3 * MROWS * DMODEL];     // rounded inputs
__device__ __align__(16) float g_Wt[(size_t)3 * DMODEL * DMODEL];    // [which][n=h*64+e][d]
__device__ __align__(16) float g_WOt[(size_t)DMODEL * DMODEL];       // [c][d]
__device__ __align__(16) float g_Q[(size_t)BH * SEQ * DHEAD];
__device__ __align__(16) float g_K[(size_t)BH * SEQ * DHEAD];
__device__ __align__(16) float g_V[(size_t)BH * SEQ * DHEAD];
__device__ __align__(16) float g_Vt[(size_t)BH * DHEAD * SEQ];       // [bh][e][k], scaled by 1/den
__device__ __align__(16) float g_P[(size_t)BH * SEQ * SEQ];          // exp(scores), causal
__device__ __align__(16) float g_Ocat[(size_t)MROWS * DMODEL];

// ---------------- helpers ---------------------------------------------------
__device__ __forceinline__ float rtf(float x) {
    uint32_t u;
    asm("cvt.rna.tf32.f32 %0, %1;" : "=r"(u) : "f"(x));
    return __uint_as_float(u);
}
__device__ __forceinline__ uint32_t swz(uint32_t o) { return o ^ ((o >> 3) & 0x70); }
__device__ __forceinline__ uint32_t smem_u32(const void* p) {
    return (uint32_t)__cvta_generic_to_shared(p);
}
__device__ __forceinline__ void cp16a(uint32_t saddr, const void* gmem) {
    asm volatile("cp.async.cg.shared.global [%0], [%1], 16;" :: "r"(saddr), "l"(gmem));
}
__device__ __forceinline__ void cp_commit() { asm volatile("cp.async.commit_group;"); }
template <int N> __device__ __forceinline__ void cp_wait() {
    asm volatile("cp.async.wait_group %0;" :: "n"(N));
}
__device__ __forceinline__ void ldsm4(uint32_t (&r)[4], uint32_t saddr) {
    asm volatile("ldmatrix.sync.aligned.m8n8.x4.shared.b16 {%0,%1,%2,%3}, [%4];"
                 : "=r"(r[0]), "=r"(r[1]), "=r"(r[2]), "=r"(r[3]) : "r"(saddr));
}
__device__ __forceinline__ void mma8(float (&c)[4], const uint32_t (&a)[4], const uint32_t* b) {
    asm volatile(
        "mma.sync.aligned.m16n8k8.row.col.f32.tf32.tf32.f32 "
        "{%0,%1,%2,%3}, {%4,%5,%6,%7}, {%8,%9}, {%0,%1,%2,%3};"
        : "+f"(c[0]), "+f"(c[1]), "+f"(c[2]), "+f"(c[3])
        : "r"(a[0]), "r"(a[1]), "r"(a[2]), "r"(a[3]), "r"(b[0]), "r"(b[1]));
}
// ldmatrix lane offsets (A: m16xk8 fragment; B: n16xk8 -> two n8 b-pairs)
#define LANE_OFFS() \
    int lane = threadIdx.x & 31; \
    int aRow = ((lane >> 3) & 1) * 8 + (lane & 7); \
    int aK16 = (lane >> 4) * 16; \
    int bRow = (lane >> 4) * 8 + (lane & 7); \
    int bK16 = ((lane >> 3) & 1) * 16; \
    int gg = lane >> 2, tt = lane & 3; (void)gg; (void)tt;

// ---------------------------------------------------------------------------
// Prologue: round inputs to tf32 (RN); transpose weights to n-major, rounded.
// ---------------------------------------------------------------------------
__global__ __launch_bounds__(256) void xround_kernel(const float4* __restrict__ q,
                                                     const float4* __restrict__ k,
                                                     const float4* __restrict__ v) {
    int which = blockIdx.z;
    const float4* src = (which == 0) ? q : (which == 1) ? k : v;
    size_t i = (size_t)blockIdx.x * 256 + threadIdx.x;
    float4 x = src[i];
    x.x = rtf(x.x); x.y = rtf(x.y); x.z = rtf(x.z); x.w = rtf(x.w);
    ((float4*)g_Xr)[(size_t)which * (MROWS * DMODEL / 4) + i] = x;
}

__global__ __launch_bounds__(256) void wt_kernel(const float* __restrict__ WQ,
                                                 const float* __restrict__ WK,
                                                 const float* __restrict__ WV) {
    int which = blockIdx.z, h = blockIdx.y, d0 = blockIdx.x * 64;
    const float* W = ((which == 0) ? WQ : (which == 1) ? WK : WV)
                     + ((size_t)h * DMODEL + d0) * DHEAD;
    __shared__ float tile[64 * 65];
    int t = threadIdx.x;
#pragma unroll
    for (int j = 0; j < 16; j++) {
        int u = t + j * 256;
        tile[(u >> 6) * 65 + (u & 63)] = W[(size_t)(u >> 6) * DHEAD + (u & 63)];
    }
    __syncthreads();
    float* out = g_Wt + (size_t)which * DMODEL * DMODEL + (size_t)h * 64 * DMODEL + d0;
#pragma unroll
    for (int j = 0; j < 16; j++) {
        int u = t + j * 256;
        int e = u >> 6, dc = u & 63;
        out[(size_t)e * DMODEL + dc] = rtf(tile[dc * 65 + e]);
    }
}

__global__ __launch_bounds__(256) void wot_kernel(const float* __restrict__ WO) {
    int d0 = blockIdx.x * 64, c0 = blockIdx.y * 64;
    __shared__ float tile[64 * 65];
    int t = threadIdx.x;
#pragma unroll
    for (int j = 0; j < 16; j++) {
        int u = t + j * 256;
        tile[(u >> 6) * 65 + (u & 63)] = WO[(size_t)(d0 + (u >> 6)) * DMODEL + c0 + (u & 63)];
    }
    __syncthreads();
#pragma unroll
    for (int j = 0; j < 16; j++) {
        int u = t + j * 256;
        int cr = u >> 6, dc = u & 63;
        g_WOt[(size_t)(c0 + cr) * DMODEL + d0 + dc] = rtf(tile[dc * 65 + cr]);
    }
}

// ---------------------------------------------------------------------------
// mm_kernel: C[128x128] = A[128xK] * B[n-major 128xK]^T, K=1024, BK=32, 2-stage.
// MODE 0: projections (which=blockIdx.z; epilogue -> g_Q/g_K/g_V, tf32-rounded)
// MODE 1: output projection -> Cout fp32
// ---------------------------------------------------------------------------
template <int MODE>
__global__ __launch_bounds__(256, 2) void mm_kernel(float* __restrict__ Cout) {
    extern __shared__ float sm[];
    uint32_t sA = smem_u32(sm);
    uint32_t sB = sA + 2 * 128 * 32 * 4;

    int t = threadIdx.x, wid = t >> 5;
    int wm = wid & 1, wn = wid >> 1;           // 2 x 4 warps -> 128x128, warp 64x32
    int mt = blockIdx.x, nt = blockIdx.y, which = blockIdx.z;
    int m0 = mt * 128, n0 = nt * 128;
    LANE_OFFS();

    const float* A = ((MODE == 0) ? g_Xr + (size_t)which * MROWS * DMODEL : g_Ocat)
                     + (size_t)m0 * DMODEL;
    const float* B = ((MODE == 0) ? g_Wt + (size_t)which * DMODEL * DMODEL : g_WOt)
                     + (size_t)n0 * DMODEL;

    float acc[4][4][4];
#pragma unroll
    for (int mi = 0; mi < 4; mi++)
#pragma unroll
        for (int nj = 0; nj < 4; nj++)
#pragma unroll
            for (int e = 0; e < 4; e++) acc[mi][nj][e] = 0.0f;

    auto issue = [&](int kk, int s) {
        uint32_t bA = sA + s * (128 * 32 * 4);
        uint32_t bB = sB + s * (128 * 32 * 4);
#pragma unroll
        for (int j = 0; j < 4; j++) {
            int u = t + j * 256;
            int row = u >> 3, at = u & 7;
            uint32_t off = swz(row * 128 + at * 16);
            cp16a(bA + off, A + (size_t)row * DMODEL + kk + at * 4);
            cp16a(bB + off, B + (size_t)row * DMODEL + kk + at * 4);
        }
    };

    uint32_t aOffU = (uint32_t)(wm * 64 + aRow) * 128 + aK16;
    uint32_t bOffU = (uint32_t)(wn * 32 + bRow) * 128 + bK16;

    issue(0, 0); cp_commit();
#pragma unroll 1
    for (int it = 0; it < 32; it++) {
        if (it < 31) { issue((it + 1) * 32, (it + 1) & 1); cp_commit(); cp_wait<1>(); }
        else cp_wait<0>();
        __syncthreads();
        uint32_t bA = sA + (it & 1) * (128 * 32 * 4);
        uint32_t bB = sB + (it & 1) * (128 * 32 * 4);
#pragma unroll
        for (int slab = 0; slab < 4; slab++) {
            uint32_t a[4][4], b[2][4];
#pragma unroll
            for (int mi = 0; mi < 4; mi++)
                ldsm4(a[mi], bA + swz(aOffU + mi * 2048 + slab * 32));
#pragma unroll
            for (int g2 = 0; g2 < 2; g2++)
                ldsm4(b[g2], bB + swz(bOffU + g2 * 2048 + slab * 32));
#pragma unroll
            for (int mi = 0; mi < 4; mi++)
#pragma unroll
                for (int nj = 0; nj < 4; nj++)
                    mma8(acc[mi][nj], a[mi], &b[nj >> 1][(nj & 1) * 2]);
        }
        __syncthreads();
    }

#pragma unroll
    for (int mi = 0; mi < 4; mi++) {
        int mrow = m0 + wm * 64 + mi * 16 + gg;
#pragma unroll
        for (int nj = 0; nj < 4; nj++) {
            int col = n0 + wn * 32 + nj * 8 + 2 * tt;
            if (MODE == 0) {
                int b = mrow >> 11, s = mrow & (SEQ - 1);
                int h = col >> 6, e = col & 63;
                float* outp = (which == 0) ? g_Q : (which == 1) ? g_K : g_V;
                float* d0 = outp + ((size_t)(b * NHEAD + h) * SEQ + s) * DHEAD + e;
                float2 v0 = make_float2(rtf(acc[mi][nj][0]), rtf(acc[mi][nj][1]));
                float2 v1 = make_float2(rtf(acc[mi][nj][2]), rtf(acc[mi][nj][3]));
                *(float2*)d0 = v0;
                *(float2*)(d0 + 8 * DHEAD) = v1;
            } else {
                float* d0 = Cout + (size_t)mrow * DMODEL + col;
                *(float2*)d0 = make_float2(acc[mi][nj][0], acc[mi][nj][1]);
                *(float2*)(d0 + 8 * DMODEL) = make_float2(acc[mi][nj][2], acc[mi][nj][3]);
            }
        }
    }
}

// ---------------------------------------------------------------------------
// den_kernel: per (64-wide k-stripe kt, bh):
//   S = Q K^T (mma), P = exp((S + (k-q))*SCALE) -> g_P, column sums -> 1/den,
//   then V stripe scaled by 1/den and transposed into g_Vt[bh][e][k].
// ---------------------------------------------------------------------------
__global__ __launch_bounds__(256, 2) void den_kernel() {
    int kt = blockIdx.x;          // kt=0 heaviest first
    int bh = blockIdx.y;

    extern __shared__ float sm[];
    float* Ks = sm;                          // [2][64][32]  (16KB)
    float* Qs = sm + 64 * 64;                // [2][128][32] (32KB)
    float* Ss = sm + 64 * 64 + 128 * 64;     // [128][64] scores / [64][65] V staging
    __shared__ float red[256];
    __shared__ float invs[64];
    uint32_t sK = smem_u32(Ks), sQ = smem_u32(Qs);

    int t = threadIdx.x, wid = t >> 5;
    int wm = wid & 3, wn = wid >> 2;         // 4 x 2 warps -> 128q x 64k, warp 32x32
    LANE_OFFS();

    const float* Qg = g_Q + (size_t)bh * SEQ * DHEAD;
    const float* Kg = g_K + ((size_t)bh * SEQ + kt * 64) * DHEAD;
    float* Pb = g_P + (size_t)bh * SEQ * SEQ + kt * 64;

    auto issueQ = [&](int qt) {
        const float* src = Qg + (size_t)qt * 128 * DHEAD;
#pragma unroll
        for (int j = 0; j < 8; j++) {
            int u = t + j * 256;
            int row = u >> 4, at = u & 15;
            cp16a(sQ + (at >> 3) * 16384 + swz(row * 128 + (at & 7) * 16),
                  src + (size_t)row * DHEAD + at * 4);
        }
    };

#pragma unroll
    for (int j = 0; j < 4; j++) {
        int u = t + j * 256;
        int row = u >> 4, at = u & 15;
        cp16a(sK + (at >> 3) * 8192 + swz(row * 128 + (at & 7) * 16),
              Kg + (size_t)row * DHEAD + at * 4);
    }
    int qt0 = kt >> 1;
    issueQ(qt0); cp_commit(); cp_wait<0>(); __syncthreads();

    uint32_t aOffU = (uint32_t)(wm * 32 + aRow) * 128 + aK16;
    uint32_t bOffU = (uint32_t)(wn * 32 + bRow) * 128 + bK16;

    int col = t & 63, ro = t >> 6;
    int kglob = kt * 64 + col;
    float part = 0.0f;

#pragma unroll 1
    for (int qt = qt0; qt < SEQ / 128; qt++) {
        float acc[2][4][4];
#pragma unroll
        for (int mi = 0; mi < 2; mi++)
#pragma unroll
            for (int nj = 0; nj < 4; nj++)
#pragma unroll
                for (int e = 0; e < 4; e++) acc[mi][nj][e] = 0.0f;

#pragma unroll
        for (int panel = 0; panel < 2; panel++) {
            uint32_t baQ = sQ + panel * 16384, baK = sK + panel * 8192;
#pragma unroll
            for (int slab = 0; slab < 4; slab++) {
                uint32_t a[2][4], b[2][4];
                ldsm4(a[0], baQ + swz(aOffU + slab * 32));
                ldsm4(a[1], baQ + swz(aOffU + 2048 + slab * 32));
                ldsm4(b[0], baK + swz(bOffU + slab * 32));
                ldsm4(b[1], baK + swz(bOffU + 2048 + slab * 32));
#pragma unroll
                for (int mi = 0; mi < 2; mi++)
#pragma unroll
                    for (int nj = 0; nj < 4; nj++)
                        mma8(acc[mi][nj], a[mi], &b[nj >> 1][(nj & 1) * 2]);
            }
        }
        // scores -> Ss
#pragma unroll
        for (int mi = 0; mi < 2; mi++) {
            int row = wm * 32 + mi * 16 + gg;
#pragma unroll
            for (int nj = 0; nj < 4; nj++) {
                int cS = wn * 32 + nj * 8 + 2 * tt;
                *(float2*)&Ss[row * 64 + cS] = make_float2(acc[mi][nj][0], acc[mi][nj][1]);
                *(float2*)&Ss[(row + 8) * 64 + cS] = make_float2(acc[mi][nj][2], acc[mi][nj][3]);
            }
        }
        __syncthreads();           // Qs consumed, Ss written
        if (qt + 1 < SEQ / 128) { issueQ(qt + 1); cp_commit(); }  // overlaps exp phase

        int q0 = qt * 128;
#pragma unroll
        for (int i = 0; i < 32; i++) {
            int row = ro + i * 4;
            int q = q0 + row;
            float s = Ss[row * 64 + col];
            float v = (kglob <= q) ? __expf((s + (float)(kglob - q)) * SCALE) : 0.0f;
            part += v;
            Pb[(size_t)q * SEQ + col] = rtf(v);
        }
        cp_wait<0>(); __syncthreads();
    }

    red[t] = part;
    __syncthreads();
    if (t < 64) invs[t] = 1.0f / (red[t] + red[t + 64] + red[t + 128] + red[t + 192]);
    __syncthreads();

    // scale + transpose V stripe into g_Vt (staging in Ss, pitch 65)
    const float* Vg = g_V + ((size_t)bh * SEQ + kt * 64) * DHEAD;
#pragma unroll
    for (int j = 0; j < 4; j++) {
        int u = t + j * 256;
        int r = u >> 4, e4 = (u & 15) * 4;
        float4 v = *(const float4*)&Vg[(size_t)r * DHEAD + e4];
        float iv = invs[r];
        Ss[r * 65 + e4 + 0] = rtf(v.x * iv);
        Ss[r * 65 + e4 + 1] = rtf(v.y * iv);
        Ss[r * 65 + e4 + 2] = rtf(v.z * iv);
        Ss[r * 65 + e4 + 3] = rtf(v.w * iv);
    }
    __syncthreads();
    float* Vt = g_Vt + (size_t)bh * DHEAD * SEQ + kt * 64;
#pragma unroll
    for (int er = 0; er < 8; er++) {
        int e = wid * 8 + er;
#pragma unroll
        for (int half = 0; half < 2; half++) {
            int r = lane + half * 32;
            Vt[(size_t)e * SEQ + r] = Ss[r * 65 + e];
        }
    }
}

// ---------------------------------------------------------------------------
// pv_kernel: Ocat[128q x 64e] = P[q, 0..(2qt+2)*64) @ Vt^T, BK=64, 2-stage.
// ---------------------------------------------------------------------------
__global__ __launch_bounds__(256, 2) void pv_kernel() {
    int qt = (int)gridDim.x - 1 - blockIdx.x;   // heaviest first
    int bh = blockIdx.y;
    int b = bh >> 4, h = bh & 15;

    extern __shared__ float sm[];
    uint32_t sP = smem_u32(sm);                 // [2 stages][2 panels][128][32] (64KB)
    uint32_t sV = sP + 2 * 2 * 128 * 32 * 4;    // [2 stages][2 panels][64][32] (32KB)

    int t = threadIdx.x, wid = t >> 5;
    int wm = wid & 3, wn = wid >> 2;            // 4x2 -> 128x64, warp 32x32
    LANE_OFFS();

    const float* Pg = g_P + ((size_t)bh * SEQ + qt * 128) * SEQ;
    const float* Vtg = g_Vt + (size_t)bh * DHEAD * SEQ;

    float acc[2][4][4];
#pragma unroll
    for (int mi = 0; mi < 2; mi++)
#pragma unroll
        for (int nj = 0; nj < 4; nj++)
#pragma unroll
            for (int e = 0; e < 4; e++) acc[mi][nj][e] = 0.0f;

    int niter = 2 * qt + 2;

    auto issue = [&](int ki, int s) {
        uint32_t bP = sP + s * 32768;
#pragma unroll
        for (int j = 0; j < 8; j++) {
            int u = t + j * 256;
            int row = u >> 4, at = u & 15;
            cp16a(bP + (at >> 3) * 16384 + swz(row * 128 + (at & 7) * 16),
                  Pg + (size_t)row * SEQ + ki * 64 + at * 4);
        }
        uint32_t bV = sV + s * 16384;
#pragma unroll
        for (int j = 0; j < 4; j++) {
            int u = t + j * 256;
            int row = u >> 4, at = u & 15;
            cp16a(bV + (at >> 3) * 8192 + swz(row * 128 + (at & 7) * 16),
                  Vtg + (size_t)row * SEQ + ki * 64 + at * 4);
        }
    };

    uint32_t aOffU = (uint32_t)(wm * 32 + aRow) * 128 + aK16;
    uint32_t bOffU = (uint32_t)(wn * 32 + bRow) * 128 + bK16;

    issue(0, 0); cp_commit();
#pragma unroll 1
    for (int it = 0; it < niter; it++) {
        if (it + 1 < niter) { issue(it + 1, (it + 1) & 1); cp_commit(); cp_wait<1>(); }
        else cp_wait<0>();
        __syncthreads();
        uint32_t bP = sP + (it & 1) * 32768;
        uint32_t bV = sV + (it & 1) * 16384;
#pragma unroll
        for (int panel = 0; panel < 2; panel++) {
            uint32_t baP = bP + panel * 16384, baV = bV + panel * 8192;
#pragma unroll
            for (int slab = 0; slab < 4; slab++) {
                uint32_t a[2][4], bfr[2][4];
                ldsm4(a[0], baP + swz(aOffU + slab * 32));
                ldsm4(a[1], baP + swz(aOffU + 2048 + slab * 32));
                ldsm4(bfr[0], baV + swz(bOffU + slab * 32));
                ldsm4(bfr[1], baV + swz(bOffU + 2048 + slab * 32));
#pragma unroll
                for (int mi = 0; mi < 2; mi++)
#pragma unroll
                    for (int nj = 0; nj < 4; nj++)
                        mma8(acc[mi][nj], a[mi], &bfr[nj >> 1][(nj & 1) * 2]);
            }
        }
        __syncthreads();
    }

#pragma unroll
    for (int mi = 0; mi < 2; mi++) {
        int row = qt * 128 + wm * 32 + mi * 16 + gg;
#pragma unroll
        for (int nj = 0; nj < 4; nj++) {
            int colL = wn * 32 + nj * 8 + 2 * tt;
            float* d0 = g_Ocat + ((size_t)(b * SEQ) + row) * DMODEL + h * 64 + colL;
            *(float2*)d0 = make_float2(rtf(acc[mi][nj][0]), rtf(acc[mi][nj][1]));
            *(float2*)(d0 + 8 * DMODEL) = make_float2(rtf(acc[mi][nj][2]), rtf(acc[mi][nj][3]));
        }
    }
}

// ---------------------------------------------------------------------------
// Launch. Inputs: keys, queries, values, WQ, WK, WV, WO, masking
// ---------------------------------------------------------------------------
extern "C" void kernel_launch(void* const* d_in, const int* in_sizes, int n_in,
                              void* d_out, int out_size) {
    const float* keys    = (const float*)d_in[0];
    const float* queries = (const float*)d_in[1];
    const float* values  = (const float*)d_in[2];
    const float* WQ      = (const float*)d_in[3];
    const float* WK      = (const float*)d_in[4];
    const float* WV      = (const float*)d_in[5];
    const float* WO      = (const float*)d_in[6];
    float* out = (float*)d_out;
    (void)in_sizes; (void)n_in; (void)out_size;

    const int mmSmem  = 2 * 128 * 32 * 4 * 2;                       // 65536
    const int denSmem = (64 * 64 + 128 * 64 + 128 * 64) * 4;        // 81920
    const int pvSmem  = (2 * 2 * 128 * 32 + 2 * 2 * 64 * 32) * 4;   // 98304
    cudaFuncSetAttribute(mm_kernel<0>, cudaFuncAttributeMaxDynamicSharedMemorySize, mmSmem);
    cudaFuncSetAttribute(mm_kernel<1>, cudaFuncAttributeMaxDynamicSharedMemorySize, mmSmem);
    cudaFuncSetAttribute(den_kernel,   cudaFuncAttributeMaxDynamicSharedMemorySize, denSmem);
    cudaFuncSetAttribute(pv_kernel,    cudaFuncAttributeMaxDynamicSharedMemorySize, pvSmem);

    // prologue
    xround_kernel<<<dim3(MROWS * DMODEL / 4 / 256, 1, 3), 256>>>(
        (const float4*)queries, (const float4*)keys, (const float4*)values);
    wt_kernel<<<dim3(DMODEL / 64, NHEAD, 3), 256>>>(WQ, WK, WV);
    wot_kernel<<<dim3(DMODEL / 64, DMODEL / 64), 256>>>(WO);

    // projections
    mm_kernel<0><<<dim3(MROWS / 128, DMODEL / 128, 3), 256, mmSmem>>>(nullptr);

    // attention
    den_kernel<<<dim3(SEQ / 64, BH), 256, denSmem>>>();
    pv_kernel<<<dim3(SEQ / 128, BH), 256, pvSmem>>>();

    // output projection
    mm_kernel<1><<<dim3(MROWS / 128, DMODEL / 128, 1), 256, mmSmem>>>(out);
}

// round 8
// speedup vs baseline: 2.9625x; 1.2939x over previous
#include <cuda_runtime.h>
#include <cuda_fp16.h>
#include <cstdint>
#include <cstddef>

#define BATCH  2
#define SEQ    2048
#define DMODEL 1024
#define NHEAD  16
#define DHEAD  64
#define BH     (BATCH*NHEAD)
#define MROWS  (BATCH*SEQ)
#define SCALE  0.022097086912079608f   // 1/sqrt(2048)

// ---------------- scratch (device globals; allocation-free rule) -----------
__device__ __align__(16) float  g_Xr[(size_t)3 * MROWS * DMODEL];    // tf32-rounded inputs
__device__ __align__(16) float  g_Wt[(size_t)3 * DMODEL * DMODEL];   // [which][n=h*64+e][d]
__device__ __align__(16) float  g_WOt[(size_t)DMODEL * DMODEL];      // [c][d]
__device__ __align__(16) __half g_Qh[(size_t)BH * SEQ * DHEAD];
__device__ __align__(16) __half g_Kh[(size_t)BH * SEQ * DHEAD];
__device__ __align__(16) float  g_V[(size_t)BH * SEQ * DHEAD];
__device__ __align__(16) __half g_Vt[(size_t)BH * DHEAD * SEQ];      // [bh][e][k], scaled 1/den
__device__ __align__(16) __half g_Ph[(size_t)BH * SEQ * SEQ];        // exp(scores) fp16
__device__ __align__(16) float  g_Ocat[(size_t)MROWS * DMODEL];

// ---------------- helpers ---------------------------------------------------
__device__ __forceinline__ float rtf(float x) {
    uint32_t u;
    asm("cvt.rna.tf32.f32 %0, %1;" : "=r"(u) : "f"(x));
    return __uint_as_float(u);
}
__device__ __forceinline__ uint32_t swz(uint32_t o) { return o ^ ((o >> 3) & 0x70); }
__device__ __forceinline__ uint32_t smem_u32(const void* p) {
    return (uint32_t)__cvta_generic_to_shared(p);
}
__device__ __forceinline__ void cp16a(uint32_t saddr, const void* gmem) {
    asm volatile("cp.async.cg.shared.global [%0], [%1], 16;" :: "r"(saddr), "l"(gmem));
}
__device__ __forceinline__ void cp_commit() { asm volatile("cp.async.commit_group;"); }
template <int N> __device__ __forceinline__ void cp_wait() {
    asm volatile("cp.async.wait_group %0;" :: "n"(N));
}
__device__ __forceinline__ void ldsm4(uint32_t (&r)[4], uint32_t saddr) {
    asm volatile("ldmatrix.sync.aligned.m8n8.x4.shared.b16 {%0,%1,%2,%3}, [%4];"
                 : "=r"(r[0]), "=r"(r[1]), "=r"(r[2]), "=r"(r[3]) : "r"(saddr));
}
__device__ __forceinline__ void mma8t(float (&c)[4], const uint32_t (&a)[4], const uint32_t* b) {
    asm volatile(
        "mma.sync.aligned.m16n8k8.row.col.f32.tf32.tf32.f32 "
        "{%0,%1,%2,%3}, {%4,%5,%6,%7}, {%8,%9}, {%0,%1,%2,%3};"
        : "+f"(c[0]), "+f"(c[1]), "+f"(c[2]), "+f"(c[3])
        : "r"(a[0]), "r"(a[1]), "r"(a[2]), "r"(a[3]), "r"(b[0]), "r"(b[1]));
}
__device__ __forceinline__ void mma16h(float (&c)[4], const uint32_t (&a)[4], const uint32_t* b) {
    asm volatile(
        "mma.sync.aligned.m16n8k16.row.col.f32.f16.f16.f32 "
        "{%0,%1,%2,%3}, {%4,%5,%6,%7}, {%8,%9}, {%0,%1,%2,%3};"
        : "+f"(c[0]), "+f"(c[1]), "+f"(c[2]), "+f"(c[3])
        : "r"(a[0]), "r"(a[1]), "r"(a[2]), "r"(a[3]), "r"(b[0]), "r"(b[1]));
}
#define LANE_OFFS() \
    int lane = threadIdx.x & 31; \
    int aRow = ((lane >> 3) & 1) * 8 + (lane & 7); \
    int aK16 = (lane >> 4) * 16; \
    int bRow = (lane >> 4) * 8 + (lane & 7); \
    int bK16 = ((lane >> 3) & 1) * 16; \
    int gg = lane >> 2, tt = lane & 3; (void)gg; (void)tt;

// ---------------------------------------------------------------------------
// Prologue: round inputs to tf32 RN; transpose weights to n-major, rounded.
// ---------------------------------------------------------------------------
__global__ __launch_bounds__(256) void xround_kernel(const float4* __restrict__ q,
                                                     const float4* __restrict__ k,
                                                     const float4* __restrict__ v) {
    int which = blockIdx.z;
    const float4* src = (which == 0) ? q : (which == 1) ? k : v;
    size_t i = (size_t)blockIdx.x * 256 + threadIdx.x;
    float4 x = src[i];
    x.x = rtf(x.x); x.y = rtf(x.y); x.z = rtf(x.z); x.w = rtf(x.w);
    ((float4*)g_Xr)[(size_t)which * (MROWS * DMODEL / 4) + i] = x;
}

__global__ __launch_bounds__(256) void wt_kernel(const float* __restrict__ WQ,
                                                 const float* __restrict__ WK,
                                                 const float* __restrict__ WV) {
    int which = blockIdx.z, h = blockIdx.y, d0 = blockIdx.x * 64;
    const float* W = ((which == 0) ? WQ : (which == 1) ? WK : WV)
                     + ((size_t)h * DMODEL + d0) * DHEAD;
    __shared__ float tile[64 * 65];
    int t = threadIdx.x;
#pragma unroll
    for (int j = 0; j < 16; j++) {
        int u = t + j * 256;
        tile[(u >> 6) * 65 + (u & 63)] = W[(size_t)(u >> 6) * DHEAD + (u & 63)];
    }
    __syncthreads();
    float* out = g_Wt + (size_t)which * DMODEL * DMODEL + (size_t)h * 64 * DMODEL + d0;
#pragma unroll
    for (int j = 0; j < 16; j++) {
        int u = t + j * 256;
        int e = u >> 6, dc = u & 63;
        out[(size_t)e * DMODEL + dc] = rtf(tile[dc * 65 + e]);
    }
}

__global__ __launch_bounds__(256) void wot_kernel(const float* __restrict__ WO) {
    int d0 = blockIdx.x * 64, c0 = blockIdx.y * 64;
    __shared__ float tile[64 * 65];
    int t = threadIdx.x;
#pragma unroll
    for (int j = 0; j < 16; j++) {
        int u = t + j * 256;
        tile[(u >> 6) * 65 + (u & 63)] = WO[(size_t)(d0 + (u >> 6)) * DMODEL + c0 + (u & 63)];
    }
    __syncthreads();
#pragma unroll
    for (int j = 0; j < 16; j++) {
        int u = t + j * 256;
        int cr = u >> 6, dc = u & 63;
        g_WOt[(size_t)(c0 + cr) * DMODEL + d0 + dc] = rtf(tile[dc * 65 + cr]);
    }
}

// ---------------------------------------------------------------------------
// mm_kernel (tf32): C[128x128] = A[128xK] * B[n-major 128xK]^T, K=1024, BK=32.
// MODE 0: projections; which 0/1 -> fp16 g_Qh/g_Kh, which 2 -> fp32 g_V
// MODE 1: output projection -> Cout fp32
// ---------------------------------------------------------------------------
template <int MODE>
__global__ __launch_bounds__(256, 2) void mm_kernel(float* __restrict__ Cout) {
    extern __shared__ float sm[];
    uint32_t sA = smem_u32(sm);
    uint32_t sB = sA + 2 * 128 * 32 * 4;

    int t = threadIdx.x, wid = t >> 5;
    int wm = wid & 1, wn = wid >> 1;           // 2x4 warps -> 128x128, warp 64x32
    int mt = blockIdx.x, nt = blockIdx.y, which = blockIdx.z;
    int m0 = mt * 128, n0 = nt * 128;
    LANE_OFFS();

    const float* A = ((MODE == 0) ? g_Xr + (size_t)which * MROWS * DMODEL : g_Ocat)
                     + (size_t)m0 * DMODEL;
    const float* B = ((MODE == 0) ? g_Wt + (size_t)which * DMODEL * DMODEL : g_WOt)
                     + (size_t)n0 * DMODEL;

    float acc[4][4][4];
#pragma unroll
    for (int mi = 0; mi < 4; mi++)
#pragma unroll
        for (int nj = 0; nj < 4; nj++)
#pragma unroll
            for (int e = 0; e < 4; e++) acc[mi][nj][e] = 0.0f;

    auto issue = [&](int kk, int s) {
        uint32_t bA = sA + s * (128 * 32 * 4);
        uint32_t bB = sB + s * (128 * 32 * 4);
#pragma unroll
        for (int j = 0; j < 4; j++) {
            int u = t + j * 256;
            int row = u >> 3, at = u & 7;
            uint32_t off = swz(row * 128 + at * 16);
            cp16a(bA + off, A + (size_t)row * DMODEL + kk + at * 4);
            cp16a(bB + off, B + (size_t)row * DMODEL + kk + at * 4);
        }
    };

    uint32_t aOffU = (uint32_t)(wm * 64 + aRow) * 128 + aK16;
    uint32_t bOffU = (uint32_t)(wn * 32 + bRow) * 128 + bK16;

    issue(0, 0); cp_commit();
#pragma unroll 1
    for (int it = 0; it < 32; it++) {
        if (it < 31) { issue((it + 1) * 32, (it + 1) & 1); cp_commit(); cp_wait<1>(); }
        else cp_wait<0>();
        __syncthreads();
        uint32_t bA = sA + (it & 1) * (128 * 32 * 4);
        uint32_t bB = sB + (it & 1) * (128 * 32 * 4);
#pragma unroll
        for (int slab = 0; slab < 4; slab++) {
            uint32_t a[4][4], b[2][4];
#pragma unroll
            for (int mi = 0; mi < 4; mi++)
                ldsm4(a[mi], bA + swz(aOffU + mi * 2048 + slab * 32));
#pragma unroll
            for (int g2 = 0; g2 < 2; g2++)
                ldsm4(b[g2], bB + swz(bOffU + g2 * 2048 + slab * 32));
#pragma unroll
            for (int mi = 0; mi < 4; mi++)
#pragma unroll
                for (int nj = 0; nj < 4; nj++)
                    mma8t(acc[mi][nj], a[mi], &b[nj >> 1][(nj & 1) * 2]);
        }
        __syncthreads();
    }

#pragma unroll
    for (int mi = 0; mi < 4; mi++) {
        int mrow = m0 + wm * 64 + mi * 16 + gg;
#pragma unroll
        for (int nj = 0; nj < 4; nj++) {
            int col = n0 + wn * 32 + nj * 8 + 2 * tt;
            if (MODE == 0) {
                int b = mrow >> 11, s = mrow & (SEQ - 1);
                int h = col >> 6, e = col & 63;
                size_t off = ((size_t)(b * NHEAD + h) * SEQ + s) * DHEAD + e;
                if (which == 2) {
                    *(float2*)&g_V[off] = make_float2(acc[mi][nj][0], acc[mi][nj][1]);
                    *(float2*)&g_V[off + 8 * DHEAD] = make_float2(acc[mi][nj][2], acc[mi][nj][3]);
                } else {
                    __half* dst = ((which == 0) ? g_Qh : g_Kh) + off;
                    *(__half2*)dst = __floats2half2_rn(acc[mi][nj][0], acc[mi][nj][1]);
                    *(__half2*)(dst + 8 * DHEAD) = __floats2half2_rn(acc[mi][nj][2], acc[mi][nj][3]);
                }
            } else {
                float* d0 = Cout + (size_t)mrow * DMODEL + col;
                *(float2*)d0 = make_float2(acc[mi][nj][0], acc[mi][nj][1]);
                *(float2*)(d0 + 8 * DMODEL) = make_float2(acc[mi][nj][2], acc[mi][nj][3]);
            }
        }
    }
}

// ---------------------------------------------------------------------------
// den_kernel (fp16 scores): per (64-wide k-stripe kt, bh):
//   S = Q K^T via mma.f16 (Q double-buffered), P = exp(...) written fp16
//   straight from fragments (LOCAL column index into Pb!); column sums in
//   registers; V stripe scaled by 1/den and transposed into g_Vt (fp16).
// ---------------------------------------------------------------------------
__global__ __launch_bounds__(256, 2) void den_kernel() {
    int kt = blockIdx.x;          // kt=0 heaviest first
    int bh = blockIdx.y;

    extern __shared__ float smf[];
    uint32_t sK = smem_u32(smf);                 // fp16 K stripe: 64*128B = 8KB
    uint32_t sQ = sK + 8192;                     // fp16 Q tiles: 2 x 16KB
    float* Vstage = (float*)((char*)smf + 8192 + 32768);  // [64][65] fp32
    __shared__ float colsum[4][64];
    __shared__ float invs[64];

    int t = threadIdx.x, wid = t >> 5;
    int wm = wid & 3, wn = wid >> 2;             // 4x2 warps -> 128q x 64k
    LANE_OFFS();

    const __half* Qg = g_Qh + (size_t)bh * SEQ * DHEAD;
    const __half* Kg = g_Kh + ((size_t)bh * SEQ + kt * 64) * DHEAD;
    __half* Pb = g_Ph + (size_t)bh * SEQ * SEQ + kt * 64;

    auto issueQ = [&](int qt, int s) {
        const __half* src = Qg + (size_t)qt * 128 * DHEAD;
        uint32_t base = sQ + s * 16384;
#pragma unroll
        for (int j = 0; j < 4; j++) {            // 128 rows x 128B = 1024 x 16B
            int u = t + j * 256;
            int row = u >> 3, ch = u & 7;
            cp16a(base + swz(row * 128 + ch * 16), src + (size_t)row * DHEAD + ch * 8);
        }
    };

#pragma unroll
    for (int j = 0; j < 2; j++) {                // K: 64 rows x 128B = 512 x 16B
        int u = t + j * 256;
        int row = u >> 3, ch = u & 7;
        cp16a(sK + swz(row * 128 + ch * 16), Kg + (size_t)row * DHEAD + ch * 8);
    }
    int qt0 = kt >> 1;
    issueQ(qt0, 0); cp_commit(); cp_wait<0>(); __syncthreads();

    uint32_t aOffU = (uint32_t)(wm * 32 + aRow) * 128 + aK16;
    uint32_t bOffU = (uint32_t)(wn * 32 + bRow) * 128 + bK16;

    float part[4][2];
#pragma unroll
    for (int nj = 0; nj < 4; nj++) { part[nj][0] = 0.0f; part[nj][1] = 0.0f; }

#pragma unroll 1
    for (int qt = qt0; qt < SEQ / 128; qt++) {
        int it = qt - qt0;
        if (qt + 1 < SEQ / 128) { issueQ(qt + 1, (it + 1) & 1); cp_commit(); }

        uint32_t baQ = sQ + (it & 1) * 16384;
        float acc[2][4][4];
#pragma unroll
        for (int mi = 0; mi < 2; mi++)
#pragma unroll
            for (int nj = 0; nj < 4; nj++)
#pragma unroll
                for (int e = 0; e < 4; e++) acc[mi][nj][e] = 0.0f;

#pragma unroll
        for (int slab = 0; slab < 4; slab++) {   // k16 x 4 = 64
            uint32_t a[2][4], b[2][4];
            ldsm4(a[0], baQ + swz(aOffU + slab * 32));
            ldsm4(a[1], baQ + swz(aOffU + 2048 + slab * 32));
            ldsm4(b[0], sK + swz(bOffU + slab * 32));
            ldsm4(b[1], sK + swz(bOffU + 2048 + slab * 32));
#pragma unroll
            for (int mi = 0; mi < 2; mi++)
#pragma unroll
                for (int nj = 0; nj < 4; nj++)
                    mma16h(acc[mi][nj], a[mi], &b[nj >> 1][(nj & 1) * 2]);
        }

        // epilogue from fragments: exp, colsum accumulate, write fp16 P.
        // NOTE: Pb already includes the kt*64 column offset -> index with kl!
        int q0 = qt * 128;
#pragma unroll
        for (int mi = 0; mi < 2; mi++) {
            int row = wm * 32 + mi * 16 + gg;
            int q = q0 + row;
#pragma unroll
            for (int nj = 0; nj < 4; nj++) {
                int kl = wn * 32 + nj * 8 + 2 * tt;   // local column within stripe
                int kg = kt * 64 + kl;                // global k (mask/bias only)
                float v0 = (kg     <= q) ? __expf((acc[mi][nj][0] + (float)(kg - q)) * SCALE) : 0.0f;
                float v1 = (kg + 1 <= q) ? __expf((acc[mi][nj][1] + (float)(kg + 1 - q)) * SCALE) : 0.0f;
                float v2 = (kg     <= q + 8) ? __expf((acc[mi][nj][2] + (float)(kg - q - 8)) * SCALE) : 0.0f;
                float v3 = (kg + 1 <= q + 8) ? __expf((acc[mi][nj][3] + (float)(kg + 1 - q - 8)) * SCALE) : 0.0f;
                part[nj][0] += v0 + v2;
                part[nj][1] += v1 + v3;
                *(__half2*)&Pb[(size_t)q * SEQ + kl] = __floats2half2_rn(v0, v1);
                *(__half2*)&Pb[(size_t)(q + 8) * SEQ + kl] = __floats2half2_rn(v2, v3);
            }
        }
        cp_wait<0>(); __syncthreads();
    }

    // reduce column sums: butterfly over the 8 row-groups, then across wm warps
#pragma unroll
    for (int nj = 0; nj < 4; nj++)
#pragma unroll
        for (int p = 0; p < 2; p++) {
            float v = part[nj][p];
            v += __shfl_xor_sync(0xffffffffu, v, 4);
            v += __shfl_xor_sync(0xffffffffu, v, 8);
            v += __shfl_xor_sync(0xffffffffu, v, 16);
            part[nj][p] = v;
        }
    if (lane < 4) {
#pragma unroll
        for (int nj = 0; nj < 4; nj++) {
            colsum[wm][wn * 32 + nj * 8 + 2 * lane]     = part[nj][0];
            colsum[wm][wn * 32 + nj * 8 + 2 * lane + 1] = part[nj][1];
        }
    }
    __syncthreads();
    if (t < 64)
        invs[t] = 1.0f / (colsum[0][t] + colsum[1][t] + colsum[2][t] + colsum[3][t]);
    __syncthreads();

    // scale + transpose V stripe -> g_Vt fp16 (staging pitch 65)
    const float* Vg = g_V + ((size_t)bh * SEQ + kt * 64) * DHEAD;
#pragma unroll
    for (int j = 0; j < 4; j++) {
        int u = t + j * 256;
        int r = u >> 4, e4 = (u & 15) * 4;
        float4 v = *(const float4*)&Vg[(size_t)r * DHEAD + e4];
        float iv = invs[r];
        Vstage[r * 65 + e4 + 0] = v.x * iv;
        Vstage[r * 65 + e4 + 1] = v.y * iv;
        Vstage[r * 65 + e4 + 2] = v.z * iv;
        Vstage[r * 65 + e4 + 3] = v.w * iv;
    }
    __syncthreads();
    __half* Vt = g_Vt + (size_t)bh * DHEAD * SEQ + kt * 64;
#pragma unroll
    for (int er = 0; er < 8; er++) {
        int e = wid * 8 + er;
#pragma unroll
        for (int half_ = 0; half_ < 2; half_++) {
            int r = lane + half_ * 32;
            Vt[(size_t)e * SEQ + r] = __float2half_rn(Vstage[r * 65 + e]);
        }
    }
}

// ---------------------------------------------------------------------------
// pv_kernel (fp16): Ocat[128q x 64e] = P @ Vt^T, BK=64, 2-stage cp.async.
// ---------------------------------------------------------------------------
__global__ __launch_bounds__(256, 2) void pv_kernel() {
    int qt = (int)gridDim.x - 1 - blockIdx.x;    // heaviest first
    int bh = blockIdx.y;
    int b = bh >> 4, h = bh & 15;

    extern __shared__ float smf[];
    uint32_t sP = smem_u32(smf);                 // [2][128 x 128B] = 32KB
    uint32_t sV = sP + 2 * 16384;                // [2][64 x 128B]  = 16KB

    int t = threadIdx.x, wid = t >> 5;
    int wm = wid & 3, wn = wid >> 2;             // 4x2 -> 128q x 64e
    LANE_OFFS();

    const __half* Pg = g_Ph + ((size_t)bh * SEQ + qt * 128) * SEQ;
    const __half* Vtg = g_Vt + (size_t)bh * DHEAD * SEQ;

    float acc[2][4][4];
#pragma unroll
    for (int mi = 0; mi < 2; mi++)
#pragma unroll
        for (int nj = 0; nj < 4; nj++)
#pragma unroll
            for (int e = 0; e < 4; e++) acc[mi][nj][e] = 0.0f;

    int niter = 2 * qt + 2;

    auto issue = [&](int ki, int s) {
        uint32_t bP = sP + s * 16384;
#pragma unroll
        for (int j = 0; j < 4; j++) {            // P: 128 rows x 128B
            int u = t + j * 256;
            int row = u >> 3, ch = u & 7;
            cp16a(bP + swz(row * 128 + ch * 16), Pg + (size_t)row * SEQ + ki * 64 + ch * 8);
        }
        uint32_t bV = sV + s * 8192;
#pragma unroll
        for (int j = 0; j < 2; j++) {            // Vt: 64 rows x 128B
            int u = t + j * 256;
            int row = u >> 3, ch = u & 7;
            cp16a(bV + swz(row * 128 + ch * 16), Vtg + (size_t)row * SEQ + ki * 64 + ch * 8);
        }
    };

    uint32_t aOffU = (uint32_t)(wm * 32 + aRow) * 128 + aK16;
    uint32_t bOffU = (uint32_t)(wn * 32 + bRow) * 128 + bK16;

    issue(0, 0); cp_commit();
#pragma unroll 1
    for (int it = 0; it < niter; it++) {
        if (it + 1 < niter) { issue(it + 1, (it + 1) & 1); cp_commit(); cp_wait<1>(); }
        else cp_wait<0>();
        __syncthreads();
        uint32_t bP = sP + (it & 1) * 16384;
        uint32_t bV = sV + (it & 1) * 8192;
#pragma unroll
        for (int slab = 0; slab < 4; slab++) {
            uint32_t a[2][4], bfr[2][4];
            ldsm4(a[0], bP + swz(aOffU + slab * 32));
            ldsm4(a[1], bP + swz(aOffU + 2048 + slab * 32));
            ldsm4(bfr[0], bV + swz(bOffU + slab * 32));
            ldsm4(bfr[1], bV + swz(bOffU + 2048 + slab * 32));
#pragma unroll
            for (int mi = 0; mi < 2; mi++)
#pragma unroll
                for (int nj = 0; nj < 4; nj++)
                    mma16h(acc[mi][nj], a[mi], &bfr[nj >> 1][(nj & 1) * 2]);
        }
        __syncthreads();
    }

#pragma unroll
    for (int mi = 0; mi < 2; mi++) {
        int row = qt * 128 + wm * 32 + mi * 16 + gg;
#pragma unroll
        for (int nj = 0; nj < 4; nj++) {
            int colL = wn * 32 + nj * 8 + 2 * tt;
            float* d0 = g_Ocat + ((size_t)(b * SEQ) + row) * DMODEL + h * 64 + colL;
            *(float2*)d0 = make_float2(rtf(acc[mi][nj][0]), rtf(acc[mi][nj][1]));
            *(float2*)(d0 + 8 * DMODEL) = make_float2(rtf(acc[mi][nj][2]), rtf(acc[mi][nj][3]));
        }
    }
}

// ---------------------------------------------------------------------------
// Launch. Inputs: keys, queries, values, WQ, WK, WV, WO, masking
// ---------------------------------------------------------------------------
extern "C" void kernel_launch(void* const* d_in, const int* in_sizes, int n_in,
                              void* d_out, int out_size) {
    const float* keys    = (const float*)d_in[0];
    const float* queries = (const float*)d_in[1];
    const float* values  = (const float*)d_in[2];
    const float* WQ      = (const float*)d_in[3];
    const float* WK      = (const float*)d_in[4];
    const float* WV      = (const float*)d_in[5];
    const float* WO      = (const float*)d_in[6];
    float* out = (float*)d_out;
    (void)in_sizes; (void)n_in; (void)out_size;

    const int mmSmem  = 2 * 128 * 32 * 4 * 2;                 // 65536
    const int denSmem = 8192 + 2 * 16384 + 64 * 65 * 4;       // 57600
    const int pvSmem  = 2 * 16384 + 2 * 8192;                 // 49152
    cudaFuncSetAttribute(mm_kernel<0>, cudaFuncAttributeMaxDynamicSharedMemorySize, mmSmem);
    cudaFuncSetAttribute(mm_kernel<1>, cudaFuncAttributeMaxDynamicSharedMemorySize, mmSmem);
    cudaFuncSetAttribute(den_kernel,   cudaFuncAttributeMaxDynamicSharedMemorySize, denSmem);
    cudaFuncSetAttribute(pv_kernel,    cudaFuncAttributeMaxDynamicSharedMemorySize, pvSmem);

    // prologue
    xround_kernel<<<dim3(MROWS * DMODEL / 4 / 256, 1, 3), 256>>>(
        (const float4*)queries, (const float4*)keys, (const float4*)values);
    wt_kernel<<<dim3(DMODEL / 64, NHEAD, 3), 256>>>(WQ, WK, WV);
    wot_kernel<<<dim3(DMODEL / 64, DMODEL / 64), 256>>>(WO);

    // projections (tf32)
    mm_kernel<0><<<dim3(MROWS / 128, DMODEL / 128, 3), 256, mmSmem>>>(nullptr);

    // attention (fp16)
    den_kernel<<<dim3(SEQ / 64, BH), 256, denSmem>>>();
    pv_kernel<<<dim3(SEQ / 128, BH), 256, pvSmem>>>();

    // output projection (tf32)
    mm_kernel<1><<<dim3(MROWS / 128, DMODEL / 128, 1), 256, mmSmem>>>(out);
}

// round 9
// speedup vs baseline: 3.2175x; 1.0861x over previous
#include <cuda_runtime.h>
#include <cuda_fp16.h>
#include <cstdint>
#include <cstddef>

#define BATCH  2
#define SEQ    2048
#define DMODEL 1024
#define NHEAD  16
#define DHEAD  64
#define BH     (BATCH*NHEAD)
#define MROWS  (BATCH*SEQ)
#define SCALE  0.022097086912079608f   // 1/sqrt(2048)

// ---------------- scratch (device globals; allocation-free rule) -----------
__device__ __align__(16) __half g_Xh[(size_t)2 * MROWS * DMODEL];    // fp16 queries/keys
__device__ __align__(16) __half g_Wth[(size_t)2 * DMODEL * DMODEL];  // fp16 n-major WQ/WK
__device__ __align__(16) float  g_Xr[(size_t)MROWS * DMODEL];        // tf32-rounded values
__device__ __align__(16) float  g_Wt[(size_t)DMODEL * DMODEL];       // tf32 n-major WV
__device__ __align__(16) float  g_WOt[(size_t)DMODEL * DMODEL];      // tf32 n-major WO
__device__ __align__(16) __half g_Qh[(size_t)BH * SEQ * DHEAD];
__device__ __align__(16) __half g_Kh[(size_t)BH * SEQ * DHEAD];
__device__ __align__(16) float  g_V[(size_t)BH * SEQ * DHEAD];
__device__ __align__(16) __half g_Vt[(size_t)BH * DHEAD * SEQ];      // [bh][e][k], scaled 1/den
__device__ __align__(16) __half g_Ph[(size_t)BH * SEQ * SEQ];        // exp(scores) fp16
__device__ __align__(16) float  g_Ocat[(size_t)MROWS * DMODEL];

// ---------------- helpers ---------------------------------------------------
__device__ __forceinline__ float rtf(float x) {
    uint32_t u;
    asm("cvt.rna.tf32.f32 %0, %1;" : "=r"(u) : "f"(x));
    return __uint_as_float(u);
}
__device__ __forceinline__ uint32_t swz(uint32_t o) { return o ^ ((o >> 3) & 0x70); }
__device__ __forceinline__ uint32_t smem_u32(const void* p) {
    return (uint32_t)__cvta_generic_to_shared(p);
}
__device__ __forceinline__ void cp16a(uint32_t saddr, const void* gmem) {
    asm volatile("cp.async.cg.shared.global [%0], [%1], 16;" :: "r"(saddr), "l"(gmem));
}
__device__ __forceinline__ void cp_commit() { asm volatile("cp.async.commit_group;"); }
template <int N> __device__ __forceinline__ void cp_wait() {
    asm volatile("cp.async.wait_group %0;" :: "n"(N));
}
__device__ __forceinline__ void ldsm4(uint32_t (&r)[4], uint32_t saddr) {
    asm volatile("ldmatrix.sync.aligned.m8n8.x4.shared.b16 {%0,%1,%2,%3}, [%4];"
                 : "=r"(r[0]), "=r"(r[1]), "=r"(r[2]), "=r"(r[3]) : "r"(saddr));
}
__device__ __forceinline__ void mma8t(float (&c)[4], const uint32_t (&a)[4], const uint32_t* b) {
    asm volatile(
        "mma.sync.aligned.m16n8k8.row.col.f32.tf32.tf32.f32 "
        "{%0,%1,%2,%3}, {%4,%5,%6,%7}, {%8,%9}, {%0,%1,%2,%3};"
        : "+f"(c[0]), "+f"(c[1]), "+f"(c[2]), "+f"(c[3])
        : "r"(a[0]), "r"(a[1]), "r"(a[2]), "r"(a[3]), "r"(b[0]), "r"(b[1]));
}
__device__ __forceinline__ void mma16h(float (&c)[4], const uint32_t (&a)[4], const uint32_t* b) {
    asm volatile(
        "mma.sync.aligned.m16n8k16.row.col.f32.f16.f16.f32 "
        "{%0,%1,%2,%3}, {%4,%5,%6,%7}, {%8,%9}, {%0,%1,%2,%3};"
        : "+f"(c[0]), "+f"(c[1]), "+f"(c[2]), "+f"(c[3])
        : "r"(a[0]), "r"(a[1]), "r"(a[2]), "r"(a[3]), "r"(b[0]), "r"(b[1]));
}
#define LANE_OFFS() \
    int lane = threadIdx.x & 31; \
    int aRow = ((lane >> 3) & 1) * 8 + (lane & 7); \
    int aK16 = (lane >> 4) * 16; \
    int bRow = (lane >> 4) * 8 + (lane & 7); \
    int bK16 = ((lane >> 3) & 1) * 16; \
    int gg = lane >> 2, tt = lane & 3; (void)gg; (void)tt;

// ---------------------------------------------------------------------------
// Prologue conversions
// ---------------------------------------------------------------------------
__global__ __launch_bounds__(256) void xhalf_kernel(const float4* __restrict__ q,
                                                    const float4* __restrict__ k) {
    int which = blockIdx.z;
    const float4* src = (which == 0) ? q : k;
    size_t i = (size_t)blockIdx.x * 256 + threadIdx.x;
    float4 x = src[i];
    __half* dst = g_Xh + (size_t)which * MROWS * DMODEL + i * 4;
    *(__half2*)dst = __floats2half2_rn(x.x, x.y);
    *(__half2*)(dst + 2) = __floats2half2_rn(x.z, x.w);
}

__global__ __launch_bounds__(256) void xroundv_kernel(const float4* __restrict__ v) {
    size_t i = (size_t)blockIdx.x * 256 + threadIdx.x;
    float4 x = v[i];
    x.x = rtf(x.x); x.y = rtf(x.y); x.z = rtf(x.z); x.w = rtf(x.w);
    ((float4*)g_Xr)[i] = x;
}

// W[h][d][e] -> fp16 n-major [h*64+e][d]. grid (16 dtile, 16 head, 2)
__global__ __launch_bounds__(256) void wthalf_kernel(const float* __restrict__ WQ,
                                                     const float* __restrict__ WK) {
    int which = blockIdx.z, h = blockIdx.y, d0 = blockIdx.x * 64;
    const float* W = ((which == 0) ? WQ : WK) + ((size_t)h * DMODEL + d0) * DHEAD;
    __shared__ float tile[64 * 65];
    int t = threadIdx.x;
#pragma unroll
    for (int j = 0; j < 16; j++) {
        int u = t + j * 256;
        tile[(u >> 6) * 65 + (u & 63)] = W[(size_t)(u >> 6) * DHEAD + (u & 63)];
    }
    __syncthreads();
    __half* out = g_Wth + (size_t)which * DMODEL * DMODEL + (size_t)h * 64 * DMODEL + d0;
#pragma unroll
    for (int j = 0; j < 16; j++) {
        int u = t + j * 256;
        int e = u >> 6, dc = u & 63;
        out[(size_t)e * DMODEL + dc] = __float2half_rn(tile[dc * 65 + e]);
    }
}

// WV -> tf32 n-major [h*64+e][d]
__global__ __launch_bounds__(256) void wtv_kernel(const float* __restrict__ WV) {
    int h = blockIdx.y, d0 = blockIdx.x * 64;
    const float* W = WV + ((size_t)h * DMODEL + d0) * DHEAD;
    __shared__ float tile[64 * 65];
    int t = threadIdx.x;
#pragma unroll
    for (int j = 0; j < 16; j++) {
        int u = t + j * 256;
        tile[(u >> 6) * 65 + (u & 63)] = W[(size_t)(u >> 6) * DHEAD + (u & 63)];
    }
    __syncthreads();
    float* out = g_Wt + (size_t)h * 64 * DMODEL + d0;
#pragma unroll
    for (int j = 0; j < 16; j++) {
        int u = t + j * 256;
        int e = u >> 6, dc = u & 63;
        out[(size_t)e * DMODEL + dc] = rtf(tile[dc * 65 + e]);
    }
}

__global__ __launch_bounds__(256) void wot_kernel(const float* __restrict__ WO) {
    int d0 = blockIdx.x * 64, c0 = blockIdx.y * 64;
    __shared__ float tile[64 * 65];
    int t = threadIdx.x;
#pragma unroll
    for (int j = 0; j < 16; j++) {
        int u = t + j * 256;
        tile[(u >> 6) * 65 + (u & 63)] = WO[(size_t)(d0 + (u >> 6)) * DMODEL + c0 + (u & 63)];
    }
    __syncthreads();
#pragma unroll
    for (int j = 0; j < 16; j++) {
        int u = t + j * 256;
        int cr = u >> 6, dc = u & 63;
        g_WOt[(size_t)(c0 + cr) * DMODEL + d0 + dc] = rtf(tile[dc * 65 + cr]);
    }
}

// ---------------------------------------------------------------------------
// mmh_kernel (fp16): Q/K projections. C[128x128] = A[128x1024] * B[128x1024]^T,
// BK=64 per stage, 2-stage cp.async. which = blockIdx.z (0->g_Qh, 1->g_Kh).
// ---------------------------------------------------------------------------
__global__ __launch_bounds__(256, 2) void mmh_kernel() {
    extern __shared__ float smf[];
    uint32_t sA = smem_u32(smf);           // [2][128 x 128B] = 32KB
    uint32_t sB = sA + 2 * 16384;          // [2][128 x 128B] = 32KB

    int t = threadIdx.x, wid = t >> 5;
    int wm = wid & 1, wn = wid >> 1;       // 2x4 warps -> 128x128, warp 64x32
    int m0 = blockIdx.x * 128, n0 = blockIdx.y * 128, which = blockIdx.z;
    LANE_OFFS();

    const __half* A = g_Xh + (size_t)which * MROWS * DMODEL + (size_t)m0 * DMODEL;
    const __half* B = g_Wth + (size_t)which * DMODEL * DMODEL + (size_t)n0 * DMODEL;

    float acc[4][4][4];
#pragma unroll
    for (int mi = 0; mi < 4; mi++)
#pragma unroll
        for (int nj = 0; nj < 4; nj++)
#pragma unroll
            for (int e = 0; e < 4; e++) acc[mi][nj][e] = 0.0f;

    auto issue = [&](int kk, int s) {
        uint32_t bA = sA + s * 16384;
        uint32_t bB = sB + s * 16384;
#pragma unroll
        for (int j = 0; j < 4; j++) {
            int u = t + j * 256;
            int row = u >> 3, ch = u & 7;
            uint32_t off = swz(row * 128 + ch * 16);
            cp16a(bA + off, A + (size_t)row * DMODEL + kk + ch * 8);
            cp16a(bB + off, B + (size_t)row * DMODEL + kk + ch * 8);
        }
    };

    uint32_t aOffU = (uint32_t)(wm * 64 + aRow) * 128 + aK16;
    uint32_t bOffU = (uint32_t)(wn * 32 + bRow) * 128 + bK16;

    issue(0, 0); cp_commit();
#pragma unroll 1
    for (int it = 0; it < 16; it++) {
        if (it < 15) { issue((it + 1) * 64, (it + 1) & 1); cp_commit(); cp_wait<1>(); }
        else cp_wait<0>();
        __syncthreads();
        uint32_t bA = sA + (it & 1) * 16384;
        uint32_t bB = sB + (it & 1) * 16384;
#pragma unroll
        for (int slab = 0; slab < 4; slab++) {   // 4 x k16 = 64
            uint32_t a[4][4], b[2][4];
#pragma unroll
            for (int mi = 0; mi < 4; mi++)
                ldsm4(a[mi], bA + swz(aOffU + mi * 2048 + slab * 32));
#pragma unroll
            for (int g2 = 0; g2 < 2; g2++)
                ldsm4(b[g2], bB + swz(bOffU + g2 * 2048 + slab * 32));
#pragma unroll
            for (int mi = 0; mi < 4; mi++)
#pragma unroll
                for (int nj = 0; nj < 4; nj++)
                    mma16h(acc[mi][nj], a[mi], &b[nj >> 1][(nj & 1) * 2]);
        }
        __syncthreads();
    }

#pragma unroll
    for (int mi = 0; mi < 4; mi++) {
        int mrow = m0 + wm * 64 + mi * 16 + gg;
#pragma unroll
        for (int nj = 0; nj < 4; nj++) {
            int col = n0 + wn * 32 + nj * 8 + 2 * tt;
            int b = mrow >> 11, s = mrow & (SEQ - 1);
            int h = col >> 6, e = col & 63;
            __half* dst = ((which == 0) ? g_Qh : g_Kh)
                          + ((size_t)(b * NHEAD + h) * SEQ + s) * DHEAD + e;
            *(__half2*)dst = __floats2half2_rn(acc[mi][nj][0], acc[mi][nj][1]);
            *(__half2*)(dst + 8 * DHEAD) = __floats2half2_rn(acc[mi][nj][2], acc[mi][nj][3]);
        }
    }
}

// ---------------------------------------------------------------------------
// mm_kernel (tf32): MODE 0: V projection -> g_V fp32. MODE 1: out proj -> Cout.
// C[128x128] = A[128x1024] * B[n-major 128x1024]^T, BK=32, 2-stage.
// ---------------------------------------------------------------------------
template <int MODE>
__global__ __launch_bounds__(256, 2) void mm_kernel(float* __restrict__ Cout) {
    extern __shared__ float sm[];
    uint32_t sA = smem_u32(sm);
    uint32_t sB = sA + 2 * 128 * 32 * 4;

    int t = threadIdx.x, wid = t >> 5;
    int wm = wid & 1, wn = wid >> 1;
    int m0 = blockIdx.x * 128, n0 = blockIdx.y * 128;
    LANE_OFFS();

    const float* A = ((MODE == 0) ? g_Xr : g_Ocat) + (size_t)m0 * DMODEL;
    const float* B = ((MODE == 0) ? g_Wt : g_WOt) + (size_t)n0 * DMODEL;

    float acc[4][4][4];
#pragma unroll
    for (int mi = 0; mi < 4; mi++)
#pragma unroll
        for (int nj = 0; nj < 4; nj++)
#pragma unroll
            for (int e = 0; e < 4; e++) acc[mi][nj][e] = 0.0f;

    auto issue = [&](int kk, int s) {
        uint32_t bA = sA + s * (128 * 32 * 4);
        uint32_t bB = sB + s * (128 * 32 * 4);
#pragma unroll
        for (int j = 0; j < 4; j++) {
            int u = t + j * 256;
            int row = u >> 3, at = u & 7;
            uint32_t off = swz(row * 128 + at * 16);
            cp16a(bA + off, A + (size_t)row * DMODEL + kk + at * 4);
            cp16a(bB + off, B + (size_t)row * DMODEL + kk + at * 4);
        }
    };

    uint32_t aOffU = (uint32_t)(wm * 64 + aRow) * 128 + aK16;
    uint32_t bOffU = (uint32_t)(wn * 32 + bRow) * 128 + bK16;

    issue(0, 0); cp_commit();
#pragma unroll 1
    for (int it = 0; it < 32; it++) {
        if (it < 31) { issue((it + 1) * 32, (it + 1) & 1); cp_commit(); cp_wait<1>(); }
        else cp_wait<0>();
        __syncthreads();
        uint32_t bA = sA + (it & 1) * (128 * 32 * 4);
        uint32_t bB = sB + (it & 1) * (128 * 32 * 4);
#pragma unroll
        for (int slab = 0; slab < 4; slab++) {
            uint32_t a[4][4], b[2][4];
#pragma unroll
            for (int mi = 0; mi < 4; mi++)
                ldsm4(a[mi], bA + swz(aOffU + mi * 2048 + slab * 32));
#pragma unroll
            for (int g2 = 0; g2 < 2; g2++)
                ldsm4(b[g2], bB + swz(bOffU + g2 * 2048 + slab * 32));
#pragma unroll
            for (int mi = 0; mi < 4; mi++)
#pragma unroll
                for (int nj = 0; nj < 4; nj++)
                    mma8t(acc[mi][nj], a[mi], &b[nj >> 1][(nj & 1) * 2]);
        }
        __syncthreads();
    }

#pragma unroll
    for (int mi = 0; mi < 4; mi++) {
        int mrow = m0 + wm * 64 + mi * 16 + gg;
#pragma unroll
        for (int nj = 0; nj < 4; nj++) {
            int col = n0 + wn * 32 + nj * 8 + 2 * tt;
            if (MODE == 0) {
                int b = mrow >> 11, s = mrow & (SEQ - 1);
                int h = col >> 6, e = col & 63;
                size_t off = ((size_t)(b * NHEAD + h) * SEQ + s) * DHEAD + e;
                *(float2*)&g_V[off] = make_float2(acc[mi][nj][0], acc[mi][nj][1]);
                *(float2*)&g_V[off + 8 * DHEAD] = make_float2(acc[mi][nj][2], acc[mi][nj][3]);
            } else {
                float* d0 = Cout + (size_t)mrow * DMODEL + col;
                *(float2*)d0 = make_float2(acc[mi][nj][0], acc[mi][nj][1]);
                *(float2*)(d0 + 8 * DMODEL) = make_float2(acc[mi][nj][2], acc[mi][nj][3]);
            }
        }
    }
}

// ---------------------------------------------------------------------------
// den_kernel (fp16 scores): per (64-wide k-stripe kt, bh):
//   S = Q K^T via mma.f16 (Q double-buffered), P = exp(...) written fp16 from
//   fragments (LOCAL column index into Pb); colsums in registers; V stripe
//   scaled by 1/den and transposed into g_Vt (fp16).
// ---------------------------------------------------------------------------
__global__ __launch_bounds__(256, 2) void den_kernel() {
    int kt = blockIdx.x;
    int bh = blockIdx.y;

    extern __shared__ float smf[];
    uint32_t sK = smem_u32(smf);                 // fp16 K stripe: 8KB
    uint32_t sQ = sK + 8192;                     // fp16 Q tiles: 2 x 16KB
    float* Vstage = (float*)((char*)smf + 8192 + 32768);  // [64][65] fp32
    __shared__ float colsum[4][64];
    __shared__ float invs[64];

    int t = threadIdx.x, wid = t >> 5;
    int wm = wid & 3, wn = wid >> 2;             // 4x2 warps -> 128q x 64k
    LANE_OFFS();

    const __half* Qg = g_Qh + (size_t)bh * SEQ * DHEAD;
    const __half* Kg = g_Kh + ((size_t)bh * SEQ + kt * 64) * DHEAD;
    __half* Pb = g_Ph + (size_t)bh * SEQ * SEQ + kt * 64;

    auto issueQ = [&](int qt, int s) {
        const __half* src = Qg + (size_t)qt * 128 * DHEAD;
        uint32_t base = sQ + s * 16384;
#pragma unroll
        for (int j = 0; j < 4; j++) {
            int u = t + j * 256;
            int row = u >> 3, ch = u & 7;
            cp16a(base + swz(row * 128 + ch * 16), src + (size_t)row * DHEAD + ch * 8);
        }
    };

#pragma unroll
    for (int j = 0; j < 2; j++) {
        int u = t + j * 256;
        int row = u >> 3, ch = u & 7;
        cp16a(sK + swz(row * 128 + ch * 16), Kg + (size_t)row * DHEAD + ch * 8);
    }
    int qt0 = kt >> 1;
    issueQ(qt0, 0); cp_commit(); cp_wait<0>(); __syncthreads();

    uint32_t aOffU = (uint32_t)(wm * 32 + aRow) * 128 + aK16;
    uint32_t bOffU = (uint32_t)(wn * 32 + bRow) * 128 + bK16;

    float part[4][2];
#pragma unroll
    for (int nj = 0; nj < 4; nj++) { part[nj][0] = 0.0f; part[nj][1] = 0.0f; }

#pragma unroll 1
    for (int qt = qt0; qt < SEQ / 128; qt++) {
        int it = qt - qt0;
        if (qt + 1 < SEQ / 128) { issueQ(qt + 1, (it + 1) & 1); cp_commit(); }

        uint32_t baQ = sQ + (it & 1) * 16384;
        float acc[2][4][4];
#pragma unroll
        for (int mi = 0; mi < 2; mi++)
#pragma unroll
            for (int nj = 0; nj < 4; nj++)
#pragma unroll
                for (int e = 0; e < 4; e++) acc[mi][nj][e] = 0.0f;

#pragma unroll
        for (int slab = 0; slab < 4; slab++) {
            uint32_t a[2][4], b[2][4];
            ldsm4(a[0], baQ + swz(aOffU + slab * 32));
            ldsm4(a[1], baQ + swz(aOffU + 2048 + slab * 32));
            ldsm4(b[0], sK + swz(bOffU + slab * 32));
            ldsm4(b[1], sK + swz(bOffU + 2048 + slab * 32));
#pragma unroll
            for (int mi = 0; mi < 2; mi++)
#pragma unroll
                for (int nj = 0; nj < 4; nj++)
                    mma16h(acc[mi][nj], a[mi], &b[nj >> 1][(nj & 1) * 2]);
        }

        int q0 = qt * 128;
#pragma unroll
        for (int mi = 0; mi < 2; mi++) {
            int row = wm * 32 + mi * 16 + gg;
            int q = q0 + row;
#pragma unroll
            for (int nj = 0; nj < 4; nj++) {
                int kl = wn * 32 + nj * 8 + 2 * tt;
                int kg = kt * 64 + kl;
                float v0 = (kg     <= q) ? __expf((acc[mi][nj][0] + (float)(kg - q)) * SCALE) : 0.0f;
                float v1 = (kg + 1 <= q) ? __expf((acc[mi][nj][1] + (float)(kg + 1 - q)) * SCALE) : 0.0f;
                float v2 = (kg     <= q + 8) ? __expf((acc[mi][nj][2] + (float)(kg - q - 8)) * SCALE) : 0.0f;
                float v3 = (kg + 1 <= q + 8) ? __expf((acc[mi][nj][3] + (float)(kg + 1 - q - 8)) * SCALE) : 0.0f;
                part[nj][0] += v0 + v2;
                part[nj][1] += v1 + v3;
                *(__half2*)&Pb[(size_t)q * SEQ + kl] = __floats2half2_rn(v0, v1);
                *(__half2*)&Pb[(size_t)(q + 8) * SEQ + kl] = __floats2half2_rn(v2, v3);
            }
        }
        cp_wait<0>(); __syncthreads();
    }

#pragma unroll
    for (int nj = 0; nj < 4; nj++)
#pragma unroll
        for (int p = 0; p < 2; p++) {
            float v = part[nj][p];
            v += __shfl_xor_sync(0xffffffffu, v, 4);
            v += __shfl_xor_sync(0xffffffffu, v, 8);
            v += __shfl_xor_sync(0xffffffffu, v, 16);
            part[nj][p] = v;
        }
    if (lane < 4) {
#pragma unroll
        for (int nj = 0; nj < 4; nj++) {
            colsum[wm][wn * 32 + nj * 8 + 2 * lane]     = part[nj][0];
            colsum[wm][wn * 32 + nj * 8 + 2 * lane + 1] = part[nj][1];
        }
    }
    __syncthreads();
    if (t < 64)
        invs[t] = 1.0f / (colsum[0][t] + colsum[1][t] + colsum[2][t] + colsum[3][t]);
    __syncthreads();

    const float* Vg = g_V + ((size_t)bh * SEQ + kt * 64) * DHEAD;
#pragma unroll
    for (int j = 0; j < 4; j++) {
        int u = t + j * 256;
        int r = u >> 4, e4 = (u & 15) * 4;
        float4 v = *(const float4*)&Vg[(size_t)r * DHEAD + e4];
        float iv = invs[r];
        Vstage[r * 65 + e4 + 0] = v.x * iv;
        Vstage[r * 65 + e4 + 1] = v.y * iv;
        Vstage[r * 65 + e4 + 2] = v.z * iv;
        Vstage[r * 65 + e4 + 3] = v.w * iv;
    }
    __syncthreads();
    __half* Vt = g_Vt + (size_t)bh * DHEAD * SEQ + kt * 64;
#pragma unroll
    for (int er = 0; er < 8; er++) {
        int e = wid * 8 + er;
#pragma unroll
        for (int half_ = 0; half_ < 2; half_++) {
            int r = lane + half_ * 32;
            Vt[(size_t)e * SEQ + r] = __float2half_rn(Vstage[r * 65 + e]);
        }
    }
}

// ---------------------------------------------------------------------------
// pv_kernel (fp16): Ocat[128q x 64e] = P @ Vt^T, BK=64, 2-stage cp.async.
// ---------------------------------------------------------------------------
__global__ __launch_bounds__(256, 2) void pv_kernel() {
    int qt = (int)gridDim.x - 1 - blockIdx.x;
    int bh = blockIdx.y;
    int b = bh >> 4, h = bh & 15;

    extern __shared__ float smf[];
    uint32_t sP = smem_u32(smf);
    uint32_t sV = sP + 2 * 16384;

    int t = threadIdx.x, wid = t >> 5;
    int wm = wid & 3, wn = wid >> 2;
    LANE_OFFS();

    const __half* Pg = g_Ph + ((size_t)bh * SEQ + qt * 128) * SEQ;
    const __half* Vtg = g_Vt + (size_t)bh * DHEAD * SEQ;

    float acc[2][4][4];
#pragma unroll
    for (int mi = 0; mi < 2; mi++)
#pragma unroll
        for (int nj = 0; nj < 4; nj++)
#pragma unroll
            for (int e = 0; e < 4; e++) acc[mi][nj][e] = 0.0f;

    int niter = 2 * qt + 2;

    auto issue = [&](int ki, int s) {
        uint32_t bP = sP + s * 16384;
#pragma unroll
        for (int j = 0; j < 4; j++) {
            int u = t + j * 256;
            int row = u >> 3, ch = u & 7;
            cp16a(bP + swz(row * 128 + ch * 16), Pg + (size_t)row * SEQ + ki * 64 + ch * 8);
        }
        uint32_t bV = sV + s * 8192;
#pragma unroll
        for (int j = 0; j < 2; j++) {
            int u = t + j * 256;
            int row = u >> 3, ch = u & 7;
            cp16a(bV + swz(row * 128 + ch * 16), Vtg + (size_t)row * SEQ + ki * 64 + ch * 8);
        }
    };

    uint32_t aOffU = (uint32_t)(wm * 32 + aRow) * 128 + aK16;
    uint32_t bOffU = (uint32_t)(wn * 32 + bRow) * 128 + bK16;

    issue(0, 0); cp_commit();
#pragma unroll 1
    for (int it = 0; it < niter; it++) {
        if (it + 1 < niter) { issue(it + 1, (it + 1) & 1); cp_commit(); cp_wait<1>(); }
        else cp_wait<0>();
        __syncthreads();
        uint32_t bP = sP + (it & 1) * 16384;
        uint32_t bV = sV + (it & 1) * 8192;
#pragma unroll
        for (int slab = 0; slab < 4; slab++) {
            uint32_t a[2][4], bfr[2][4];
            ldsm4(a[0], bP + swz(aOffU + slab * 32));
            ldsm4(a[1], bP + swz(aOffU + 2048 + slab * 32));
            ldsm4(bfr[0], bV + swz(bOffU + slab * 32));
            ldsm4(bfr[1], bV + swz(bOffU + 2048 + slab * 32));
#pragma unroll
            for (int mi = 0; mi < 2; mi++)
#pragma unroll
                for (int nj = 0; nj < 4; nj++)
                    mma16h(acc[mi][nj], a[mi], &bfr[nj >> 1][(nj & 1) * 2]);
        }
        __syncthreads();
    }

#pragma unroll
    for (int mi = 0; mi < 2; mi++) {
        int row = qt * 128 + wm * 32 + mi * 16 + gg;
#pragma unroll
        for (int nj = 0; nj < 4; nj++) {
            int colL = wn * 32 + nj * 8 + 2 * tt;
            float* d0 = g_Ocat + ((size_t)(b * SEQ) + row) * DMODEL + h * 64 + colL;
            *(float2*)d0 = make_float2(rtf(acc[mi][nj][0]), rtf(acc[mi][nj][1]));
            *(float2*)(d0 + 8 * DMODEL) = make_float2(rtf(acc[mi][nj][2]), rtf(acc[mi][nj][3]));
        }
    }
}

// ---------------------------------------------------------------------------
// Launch. Inputs: keys, queries, values, WQ, WK, WV, WO, masking
// ---------------------------------------------------------------------------
extern "C" void kernel_launch(void* const* d_in, const int* in_sizes, int n_in,
                              void* d_out, int out_size) {
    const float* keys    = (const float*)d_in[0];
    const float* queries = (const float*)d_in[1];
    const float* values  = (const float*)d_in[2];
    const float* WQ      = (const float*)d_in[3];
    const float* WK      = (const float*)d_in[4];
    const float* WV      = (const float*)d_in[5];
    const float* WO      = (const float*)d_in[6];
    float* out = (float*)d_out;
    (void)in_sizes; (void)n_in; (void)out_size;

    const int mmSmem  = 2 * 128 * 32 * 4 * 2;                 // 65536
    const int mmhSmem = 2 * 16384 * 2;                        // 65536
    const int denSmem = 8192 + 2 * 16384 + 64 * 65 * 4;       // 57600
    const int pvSmem  = 2 * 16384 + 2 * 8192;                 // 49152
    cudaFuncSetAttribute(mm_kernel<0>, cudaFuncAttributeMaxDynamicSharedMemorySize, mmSmem);
    cudaFuncSetAttribute(mm_kernel<1>, cudaFuncAttributeMaxDynamicSharedMemorySize, mmSmem);
    cudaFuncSetAttribute(mmh_kernel,   cudaFuncAttributeMaxDynamicSharedMemorySize, mmhSmem);
    cudaFuncSetAttribute(den_kernel,   cudaFuncAttributeMaxDynamicSharedMemorySize, denSmem);
    cudaFuncSetAttribute(pv_kernel,    cudaFuncAttributeMaxDynamicSharedMemorySize, pvSmem);

    // prologue
    xhalf_kernel<<<dim3(MROWS * DMODEL / 4 / 256, 1, 2), 256>>>(
        (const float4*)queries, (const float4*)keys);
    xroundv_kernel<<<MROWS * DMODEL / 4 / 256, 256>>>((const float4*)values);
    wthalf_kernel<<<dim3(DMODEL / 64, NHEAD, 2), 256>>>(WQ, WK);
    wtv_kernel<<<dim3(DMODEL / 64, NHEAD), 256>>>(WV);
    wot_kernel<<<dim3(DMODEL / 64, DMODEL / 64), 256>>>(WO);

    // projections: Q,K fp16; V tf32
    mmh_kernel<<<dim3(MROWS / 128, DMODEL / 128, 2), 256, mmhSmem>>>();
    mm_kernel<0><<<dim3(MROWS / 128, DMODEL / 128), 256, mmSmem>>>(nullptr);

    // attention (fp16)
    den_kernel<<<dim3(SEQ / 64, BH), 256, denSmem>>>();
    pv_kernel<<<dim3(SEQ / 128, BH), 256, pvSmem>>>();

    // output projection (tf32)
    mm_kernel<1><<<dim3(MROWS / 128, DMODEL / 128), 256, mmSmem>>>(out);
}

// round 10
// speedup vs baseline: 3.5465x; 1.1023x over previous
#include <cuda_runtime.h>
#include <cuda_fp16.h>
#include <cstdint>
#include <cstddef>

#define BATCH  2
#define SEQ    2048
#define DMODEL 1024
#define NHEAD  16
#define DHEAD  64
#define BH     (BATCH*NHEAD)
#define MROWS  (BATCH*SEQ)
#define SCALE  0.022097086912079608f   // 1/sqrt(2048)

// ---------------- scratch (device globals; allocation-free rule) -----------
__device__ __align__(16) __half g_Xh[(size_t)2 * MROWS * DMODEL];    // fp16 queries/keys
__device__ __align__(16) __half g_Wth[(size_t)2 * DMODEL * DMODEL];  // fp16 n-major WQ/WK
__device__ __align__(16) float  g_Xr[(size_t)MROWS * DMODEL];        // tf32-rounded values
__device__ __align__(16) float  g_Wt[(size_t)DMODEL * DMODEL];       // tf32 n-major WV
__device__ __align__(16) __half g_WOth[(size_t)DMODEL * DMODEL];     // fp16 n-major WO
__device__ __align__(16) __half g_Qh[(size_t)BH * SEQ * DHEAD];
__device__ __align__(16) __half g_Kh[(size_t)BH * SEQ * DHEAD];
__device__ __align__(16) float  g_V[(size_t)BH * SEQ * DHEAD];
__device__ __align__(16) __half g_Vt[(size_t)BH * DHEAD * SEQ];      // [bh][e][k], scaled 1/den
__device__ __align__(16) __half g_Ph[(size_t)BH * SEQ * SEQ];        // exp(scores) fp16
__device__ __align__(16) __half g_Ocat[(size_t)MROWS * DMODEL];      // fp16 attention output

// ---------------- helpers ---------------------------------------------------
__device__ __forceinline__ float rtf(float x) {
    uint32_t u;
    asm("cvt.rna.tf32.f32 %0, %1;" : "=r"(u) : "f"(x));
    return __uint_as_float(u);
}
__device__ __forceinline__ uint32_t swz(uint32_t o) { return o ^ ((o >> 3) & 0x70); }
__device__ __forceinline__ uint32_t smem_u32(const void* p) {
    return (uint32_t)__cvta_generic_to_shared(p);
}
__device__ __forceinline__ void cp16a(uint32_t saddr, const void* gmem) {
    asm volatile("cp.async.cg.shared.global [%0], [%1], 16;" :: "r"(saddr), "l"(gmem));
}
__device__ __forceinline__ void cp_commit() { asm volatile("cp.async.commit_group;"); }
template <int N> __device__ __forceinline__ void cp_wait() {
    asm volatile("cp.async.wait_group %0;" :: "n"(N));
}
__device__ __forceinline__ void ldsm4(uint32_t (&r)[4], uint32_t saddr) {
    asm volatile("ldmatrix.sync.aligned.m8n8.x4.shared.b16 {%0,%1,%2,%3}, [%4];"
                 : "=r"(r[0]), "=r"(r[1]), "=r"(r[2]), "=r"(r[3]) : "r"(saddr));
}
__device__ __forceinline__ void mma8t(float (&c)[4], const uint32_t (&a)[4], const uint32_t* b) {
    asm volatile(
        "mma.sync.aligned.m16n8k8.row.col.f32.tf32.tf32.f32 "
        "{%0,%1,%2,%3}, {%4,%5,%6,%7}, {%8,%9}, {%0,%1,%2,%3};"
        : "+f"(c[0]), "+f"(c[1]), "+f"(c[2]), "+f"(c[3])
        : "r"(a[0]), "r"(a[1]), "r"(a[2]), "r"(a[3]), "r"(b[0]), "r"(b[1]));
}
__device__ __forceinline__ void mma16h(float (&c)[4], const uint32_t (&a)[4], const uint32_t* b) {
    asm volatile(
        "mma.sync.aligned.m16n8k16.row.col.f32.f16.f16.f32 "
        "{%0,%1,%2,%3}, {%4,%5,%6,%7}, {%8,%9}, {%0,%1,%2,%3};"
        : "+f"(c[0]), "+f"(c[1]), "+f"(c[2]), "+f"(c[3])
        : "r"(a[0]), "r"(a[1]), "r"(a[2]), "r"(a[3]), "r"(b[0]), "r"(b[1]));
}
#define LANE_OFFS() \
    int lane = threadIdx.x & 31; \
    int aRow = ((lane >> 3) & 1) * 8 + (lane & 7); \
    int aK16 = (lane >> 4) * 16; \
    int bRow = (lane >> 4) * 8 + (lane & 7); \
    int bK16 = ((lane >> 3) & 1) * 16; \
    int gg = lane >> 2, tt = lane & 3; (void)gg; (void)tt;

// ---------------------------------------------------------------------------
// Prologue: z=0 queries->fp16, z=1 keys->fp16, z=2 values->tf32
// ---------------------------------------------------------------------------
__global__ __launch_bounds__(256) void xprep_kernel(const float4* __restrict__ q,
                                                    const float4* __restrict__ k,
                                                    const float4* __restrict__ v) {
    int which = blockIdx.z;
    const float4* src = (which == 0) ? q : (which == 1) ? k : v;
    size_t i = (size_t)blockIdx.x * 256 + threadIdx.x;
    float4 x = src[i];
    if (which == 2) {
        x.x = rtf(x.x); x.y = rtf(x.y); x.z = rtf(x.z); x.w = rtf(x.w);
        ((float4*)g_Xr)[i] = x;
    } else {
        __half* dst = g_Xh + (size_t)which * MROWS * DMODEL + i * 4;
        *(__half2*)dst = __floats2half2_rn(x.x, x.y);
        *(__half2*)(dst + 2) = __floats2half2_rn(x.z, x.w);
    }
}

// W[h][d][e] -> n-major [h*64+e][d]; z=0 WQ fp16, z=1 WK fp16, z=2 WV tf32
__global__ __launch_bounds__(256) void wprep_kernel(const float* __restrict__ WQ,
                                                    const float* __restrict__ WK,
                                                    const float* __restrict__ WV) {
    int which = blockIdx.z, h = blockIdx.y, d0 = blockIdx.x * 64;
    const float* W = ((which == 0) ? WQ : (which == 1) ? WK : WV)
                     + ((size_t)h * DMODEL + d0) * DHEAD;
    __shared__ float tile[64 * 65];
    int t = threadIdx.x;
#pragma unroll
    for (int j = 0; j < 16; j++) {
        int u = t + j * 256;
        tile[(u >> 6) * 65 + (u & 63)] = W[(size_t)(u >> 6) * DHEAD + (u & 63)];
    }
    __syncthreads();
    if (which == 2) {
        float* out = g_Wt + (size_t)h * 64 * DMODEL + d0;
#pragma unroll
        for (int j = 0; j < 16; j++) {
            int u = t + j * 256;
            int e = u >> 6, dc = u & 63;
            out[(size_t)e * DMODEL + dc] = rtf(tile[dc * 65 + e]);
        }
    } else {
        __half* out = g_Wth + (size_t)which * DMODEL * DMODEL + (size_t)h * 64 * DMODEL + d0;
#pragma unroll
        for (int j = 0; j < 16; j++) {
            int u = t + j * 256;
            int e = u >> 6, dc = u & 63;
            out[(size_t)e * DMODEL + dc] = __float2half_rn(tile[dc * 65 + e]);
        }
    }
}

// WO[d][c] -> fp16 n-major [c][d]
__global__ __launch_bounds__(256) void woprep_kernel(const float* __restrict__ WO) {
    int d0 = blockIdx.x * 64, c0 = blockIdx.y * 64;
    __shared__ float tile[64 * 65];
    int t = threadIdx.x;
#pragma unroll
    for (int j = 0; j < 16; j++) {
        int u = t + j * 256;
        tile[(u >> 6) * 65 + (u & 63)] = WO[(size_t)(d0 + (u >> 6)) * DMODEL + c0 + (u & 63)];
    }
    __syncthreads();
#pragma unroll
    for (int j = 0; j < 16; j++) {
        int u = t + j * 256;
        int cr = u >> 6, dc = u & 63;
        g_WOth[(size_t)(c0 + cr) * DMODEL + d0 + dc] = __float2half_rn(tile[dc * 65 + cr]);
    }
}

// ---------------------------------------------------------------------------
// mmh_kernel (fp16, 3-stage, BK=64): C[128x128] = A[128x1024] * B[128x1024]^T.
// MODE 0: Q/K projections (which = blockIdx.z, epilogue -> g_Qh/g_Kh fp16)
// MODE 1: output projection (A = g_Ocat fp16, B = g_WOth, epilogue -> fp32 Cout)
// ---------------------------------------------------------------------------
template <int MODE>
__global__ __launch_bounds__(256, 2) void mmh_kernel(float* __restrict__ Cout) {
    extern __shared__ float smf[];
    uint32_t sA = smem_u32(smf);           // [3][128 x 128B] = 48KB
    uint32_t sB = sA + 3 * 16384;          // [3][128 x 128B] = 48KB

    int t = threadIdx.x, wid = t >> 5;
    int wm = wid & 1, wn = wid >> 1;       // 2x4 warps -> 128x128, warp 64x32
    int m0 = blockIdx.x * 128, n0 = blockIdx.y * 128, which = blockIdx.z;
    LANE_OFFS();

    const __half* A = (MODE == 0)
        ? g_Xh + (size_t)which * MROWS * DMODEL + (size_t)m0 * DMODEL
        : g_Ocat + (size_t)m0 * DMODEL;
    const __half* B = (MODE == 0)
        ? g_Wth + (size_t)which * DMODEL * DMODEL + (size_t)n0 * DMODEL
        : g_WOth + (size_t)n0 * DMODEL;

    float acc[4][4][4];
#pragma unroll
    for (int mi = 0; mi < 4; mi++)
#pragma unroll
        for (int nj = 0; nj < 4; nj++)
#pragma unroll
            for (int e = 0; e < 4; e++) acc[mi][nj][e] = 0.0f;

    auto issue = [&](int it3) {
        int s = it3 % 3;
        int kk = it3 * 64;
        uint32_t bA = sA + s * 16384;
        uint32_t bB = sB + s * 16384;
#pragma unroll
        for (int j = 0; j < 4; j++) {
            int u = t + j * 256;
            int row = u >> 3, ch = u & 7;
            uint32_t off = swz(row * 128 + ch * 16);
            cp16a(bA + off, A + (size_t)row * DMODEL + kk + ch * 8);
            cp16a(bB + off, B + (size_t)row * DMODEL + kk + ch * 8);
        }
    };

    uint32_t aOffU = (uint32_t)(wm * 64 + aRow) * 128 + aK16;
    uint32_t bOffU = (uint32_t)(wn * 32 + bRow) * 128 + bK16;

    issue(0); cp_commit();
    issue(1); cp_commit();
#pragma unroll 1
    for (int it = 0; it < 16; it++) {
        if (it + 2 < 16) { issue(it + 2); cp_commit(); cp_wait<2>(); }
        else if (it + 1 < 16) cp_wait<1>();
        else cp_wait<0>();
        __syncthreads();
        uint32_t bA = sA + (it % 3) * 16384;
        uint32_t bB = sB + (it % 3) * 16384;
#pragma unroll
        for (int slab = 0; slab < 4; slab++) {   // 4 x k16 = 64
            uint32_t a[4][4], b[2][4];
#pragma unroll
            for (int mi = 0; mi < 4; mi++)
                ldsm4(a[mi], bA + swz(aOffU + mi * 2048 + slab * 32));
#pragma unroll
            for (int g2 = 0; g2 < 2; g2++)
                ldsm4(b[g2], bB + swz(bOffU + g2 * 2048 + slab * 32));
#pragma unroll
            for (int mi = 0; mi < 4; mi++)
#pragma unroll
                for (int nj = 0; nj < 4; nj++)
                    mma16h(acc[mi][nj], a[mi], &b[nj >> 1][(nj & 1) * 2]);
        }
        __syncthreads();
    }

#pragma unroll
    for (int mi = 0; mi < 4; mi++) {
        int mrow = m0 + wm * 64 + mi * 16 + gg;
#pragma unroll
        for (int nj = 0; nj < 4; nj++) {
            int col = n0 + wn * 32 + nj * 8 + 2 * tt;
            if (MODE == 0) {
                int b = mrow >> 11, s = mrow & (SEQ - 1);
                int h = col >> 6, e = col & 63;
                __half* dst = ((which == 0) ? g_Qh : g_Kh)
                              + ((size_t)(b * NHEAD + h) * SEQ + s) * DHEAD + e;
                *(__half2*)dst = __floats2half2_rn(acc[mi][nj][0], acc[mi][nj][1]);
                *(__half2*)(dst + 8 * DHEAD) = __floats2half2_rn(acc[mi][nj][2], acc[mi][nj][3]);
            } else {
                float* d0 = Cout + (size_t)mrow * DMODEL + col;
                *(float2*)d0 = make_float2(acc[mi][nj][0], acc[mi][nj][1]);
                *(float2*)(d0 + 8 * DMODEL) = make_float2(acc[mi][nj][2], acc[mi][nj][3]);
            }
        }
    }
}

// ---------------------------------------------------------------------------
// mmv_kernel (tf32, 3-stage, BK=32): V projection -> g_V fp32.
// ---------------------------------------------------------------------------
__global__ __launch_bounds__(256, 2) void mmv_kernel() {
    extern __shared__ float sm[];
    uint32_t sA = smem_u32(sm);            // [3][128 x 128B] = 48KB
    uint32_t sB = sA + 3 * 16384;          // [3][128 x 128B] = 48KB

    int t = threadIdx.x, wid = t >> 5;
    int wm = wid & 1, wn = wid >> 1;
    int m0 = blockIdx.x * 128, n0 = blockIdx.y * 128;
    LANE_OFFS();

    const float* A = g_Xr + (size_t)m0 * DMODEL;
    const float* B = g_Wt + (size_t)n0 * DMODEL;

    float acc[4][4][4];
#pragma unroll
    for (int mi = 0; mi < 4; mi++)
#pragma unroll
        for (int nj = 0; nj < 4; nj++)
#pragma unroll
            for (int e = 0; e < 4; e++) acc[mi][nj][e] = 0.0f;

    auto issue = [&](int it3) {
        int s = it3 % 3;
        int kk = it3 * 32;
        uint32_t bA = sA + s * 16384;
        uint32_t bB = sB + s * 16384;
#pragma unroll
        for (int j = 0; j < 4; j++) {
            int u = t + j * 256;
            int row = u >> 3, at = u & 7;
            uint32_t off = swz(row * 128 + at * 16);
            cp16a(bA + off, A + (size_t)row * DMODEL + kk + at * 4);
            cp16a(bB + off, B + (size_t)row * DMODEL + kk + at * 4);
        }
    };

    uint32_t aOffU = (uint32_t)(wm * 64 + aRow) * 128 + aK16;
    uint32_t bOffU = (uint32_t)(wn * 32 + bRow) * 128 + bK16;

    issue(0); cp_commit();
    issue(1); cp_commit();
#pragma unroll 1
    for (int it = 0; it < 32; it++) {
        if (it + 2 < 32) { issue(it + 2); cp_commit(); cp_wait<2>(); }
        else if (it + 1 < 32) cp_wait<1>();
        else cp_wait<0>();
        __syncthreads();
        uint32_t bA = sA + (it % 3) * 16384;
        uint32_t bB = sB + (it % 3) * 16384;
#pragma unroll
        for (int slab = 0; slab < 4; slab++) {
            uint32_t a[4][4], b[2][4];
#pragma unroll
            for (int mi = 0; mi < 4; mi++)
                ldsm4(a[mi], bA + swz(aOffU + mi * 2048 + slab * 32));
#pragma unroll
            for (int g2 = 0; g2 < 2; g2++)
                ldsm4(b[g2], bB + swz(bOffU + g2 * 2048 + slab * 32));
#pragma unroll
            for (int mi = 0; mi < 4; mi++)
#pragma unroll
                for (int nj = 0; nj < 4; nj++)
                    mma8t(acc[mi][nj], a[mi], &b[nj >> 1][(nj & 1) * 2]);
        }
        __syncthreads();
    }

#pragma unroll
    for (int mi = 0; mi < 4; mi++) {
        int mrow = m0 + wm * 64 + mi * 16 + gg;
#pragma unroll
        for (int nj = 0; nj < 4; nj++) {
            int col = n0 + wn * 32 + nj * 8 + 2 * tt;
            int b = mrow >> 11, s = mrow & (SEQ - 1);
            int h = col >> 6, e = col & 63;
            size_t off = ((size_t)(b * NHEAD + h) * SEQ + s) * DHEAD + e;
            *(float2*)&g_V[off] = make_float2(acc[mi][nj][0], acc[mi][nj][1]);
            *(float2*)&g_V[off + 8 * DHEAD] = make_float2(acc[mi][nj][2], acc[mi][nj][3]);
        }
    }
}

// ---------------------------------------------------------------------------
// den_kernel (fp16 scores): per (64-wide k-stripe kt, bh):
//   S = Q K^T (Q double-buffered, overlapped with exp phase), P -> g_Ph fp16
//   (LOCAL column index); colsums in registers; V stripe scaled + transposed.
// ---------------------------------------------------------------------------
__global__ __launch_bounds__(256, 2) void den_kernel() {
    int kt = blockIdx.x;
    int bh = blockIdx.y;

    extern __shared__ float smf[];
    uint32_t sK = smem_u32(smf);                 // fp16 K stripe: 8KB
    uint32_t sQ = sK + 8192;                     // fp16 Q tiles: 2 x 16KB
    float* Vstage = (float*)((char*)smf + 8192 + 32768);  // [64][65] fp32
    __shared__ float colsum[4][64];
    __shared__ float invs[64];

    int t = threadIdx.x, wid = t >> 5;
    int wm = wid & 3, wn = wid >> 2;             // 4x2 warps -> 128q x 64k
    LANE_OFFS();

    const __half* Qg = g_Qh + (size_t)bh * SEQ * DHEAD;
    const __half* Kg = g_Kh + ((size_t)bh * SEQ + kt * 64) * DHEAD;
    __half* Pb = g_Ph + (size_t)bh * SEQ * SEQ + kt * 64;

    auto issueQ = [&](int qt, int s) {
        const __half* src = Qg + (size_t)qt * 128 * DHEAD;
        uint32_t base = sQ + s * 16384;
#pragma unroll
        for (int j = 0; j < 4; j++) {
            int u = t + j * 256;
            int row = u >> 3, ch = u & 7;
            cp16a(base + swz(row * 128 + ch * 16), src + (size_t)row * DHEAD + ch * 8);
        }
    };

#pragma unroll
    for (int j = 0; j < 2; j++) {
        int u = t + j * 256;
        int row = u >> 3, ch = u & 7;
        cp16a(sK + swz(row * 128 + ch * 16), Kg + (size_t)row * DHEAD + ch * 8);
    }
    int qt0 = kt >> 1;
    issueQ(qt0, 0); cp_commit(); cp_wait<0>(); __syncthreads();

    uint32_t aOffU = (uint32_t)(wm * 32 + aRow) * 128 + aK16;
    uint32_t bOffU = (uint32_t)(wn * 32 + bRow) * 128 + bK16;

    float part[4][2];
#pragma unroll
    for (int nj = 0; nj < 4; nj++) { part[nj][0] = 0.0f; part[nj][1] = 0.0f; }

#pragma unroll 1
    for (int qt = qt0; qt < SEQ / 128; qt++) {
        int it = qt - qt0;
        if (qt + 1 < SEQ / 128) { issueQ(qt + 1, (it + 1) & 1); cp_commit(); }

        uint32_t baQ = sQ + (it & 1) * 16384;
        float acc[2][4][4];
#pragma unroll
        for (int mi = 0; mi < 2; mi++)
#pragma unroll
            for (int nj = 0; nj < 4; nj++)
#pragma unroll
                for (int e = 0; e < 4; e++) acc[mi][nj][e] = 0.0f;

#pragma unroll
        for (int slab = 0; slab < 4; slab++) {
            uint32_t a[2][4], b[2][4];
            ldsm4(a[0], baQ + swz(aOffU + slab * 32));
            ldsm4(a[1], baQ + swz(aOffU + 2048 + slab * 32));
            ldsm4(b[0], sK + swz(bOffU + slab * 32));
            ldsm4(b[1], sK + swz(bOffU + 2048 + slab * 32));
#pragma unroll
            for (int mi = 0; mi < 2; mi++)
#pragma unroll
                for (int nj = 0; nj < 4; nj++)
                    mma16h(acc[mi][nj], a[mi], &b[nj >> 1][(nj & 1) * 2]);
        }

        int q0 = qt * 128;
#pragma unroll
        for (int mi = 0; mi < 2; mi++) {
            int row = wm * 32 + mi * 16 + gg;
            int q = q0 + row;
#pragma unroll
            for (int nj = 0; nj < 4; nj++) {
                int kl = wn * 32 + nj * 8 + 2 * tt;
                int kg = kt * 64 + kl;
                float v0 = (kg     <= q) ? __expf((acc[mi][nj][0] + (float)(kg - q)) * SCALE) : 0.0f;
                float v1 = (kg + 1 <= q) ? __expf((acc[mi][nj][1] + (float)(kg + 1 - q)) * SCALE) : 0.0f;
                float v2 = (kg     <= q + 8) ? __expf((acc[mi][nj][2] + (float)(kg - q - 8)) * SCALE) : 0.0f;
                float v3 = (kg + 1 <= q + 8) ? __expf((acc[mi][nj][3] + (float)(kg + 1 - q - 8)) * SCALE) : 0.0f;
                part[nj][0] += v0 + v2;
                part[nj][1] += v1 + v3;
                *(__half2*)&Pb[(size_t)q * SEQ + kl] = __floats2half2_rn(v0, v1);
                *(__half2*)&Pb[(size_t)(q + 8) * SEQ + kl] = __floats2half2_rn(v2, v3);
            }
        }
        cp_wait<0>(); __syncthreads();
    }

#pragma unroll
    for (int nj = 0; nj < 4; nj++)
#pragma unroll
        for (int p = 0; p < 2; p++) {
            float v = part[nj][p];
            v += __shfl_xor_sync(0xffffffffu, v, 4);
            v += __shfl_xor_sync(0xffffffffu, v, 8);
            v += __shfl_xor_sync(0xffffffffu, v, 16);
            part[nj][p] = v;
        }
    if (lane < 4) {
#pragma unroll
        for (int nj = 0; nj < 4; nj++) {
            colsum[wm][wn * 32 + nj * 8 + 2 * lane]     = part[nj][0];
            colsum[wm][wn * 32 + nj * 8 + 2 * lane + 1] = part[nj][1];
        }
    }
    __syncthreads();
    if (t < 64)
        invs[t] = 1.0f / (colsum[0][t] + colsum[1][t] + colsum[2][t] + colsum[3][t]);
    __syncthreads();

    const float* Vg = g_V + ((size_t)bh * SEQ + kt * 64) * DHEAD;
#pragma unroll
    for (int j = 0; j < 4; j++) {
        int u = t + j * 256;
        int r = u >> 4, e4 = (u & 15) * 4;
        float4 v = *(const float4*)&Vg[(size_t)r * DHEAD + e4];
        float iv = invs[r];
        Vstage[r * 65 + e4 + 0] = v.x * iv;
        Vstage[r * 65 + e4 + 1] = v.y * iv;
        Vstage[r * 65 + e4 + 2] = v.z * iv;
        Vstage[r * 65 + e4 + 3] = v.w * iv;
    }
    __syncthreads();
    __half* Vt = g_Vt + (size_t)bh * DHEAD * SEQ + kt * 64;
#pragma unroll
    for (int er = 0; er < 8; er++) {
        int e = wid * 8 + er;
#pragma unroll
        for (int half_ = 0; half_ < 2; half_++) {
            int r = lane + half_ * 32;
            Vt[(size_t)e * SEQ + r] = __float2half_rn(Vstage[r * 65 + e]);
        }
    }
}

// ---------------------------------------------------------------------------
// pv_kernel (fp16): Ocat[128q x 64e] = P @ Vt^T, BK=64, 2-stage cp.async.
// Epilogue writes fp16 Ocat.
// ---------------------------------------------------------------------------
__global__ __launch_bounds__(256, 2) void pv_kernel() {
    int qt = (int)gridDim.x - 1 - blockIdx.x;
    int bh = blockIdx.y;
    int b = bh >> 4, h = bh & 15;

    extern __shared__ float smf[];
    uint32_t sP = smem_u32(smf);
    uint32_t sV = sP + 2 * 16384;

    int t = threadIdx.x, wid = t >> 5;
    int wm = wid & 3, wn = wid >> 2;
    LANE_OFFS();

    const __half* Pg = g_Ph + ((size_t)bh * SEQ + qt * 128) * SEQ;
    const __half* Vtg = g_Vt + (size_t)bh * DHEAD * SEQ;

    float acc[2][4][4];
#pragma unroll
    for (int mi = 0; mi < 2; mi++)
#pragma unroll
        for (int nj = 0; nj < 4; nj++)
#pragma unroll
            for (int e = 0; e < 4; e++) acc[mi][nj][e] = 0.0f;

    int niter = 2 * qt + 2;

    auto issue = [&](int ki, int s) {
        uint32_t bP = sP + s * 16384;
#pragma unroll
        for (int j = 0; j < 4; j++) {
            int u = t + j * 256;
            int row = u >> 3, ch = u & 7;
            cp16a(bP + swz(row * 128 + ch * 16), Pg + (size_t)row * SEQ + ki * 64 + ch * 8);
        }
        uint32_t bV = sV + s * 8192;
#pragma unroll
        for (int j = 0; j < 2; j++) {
            int u = t + j * 256;
            int row = u >> 3, ch = u & 7;
            cp16a(bV + swz(row * 128 + ch * 16), Vtg + (size_t)row * SEQ + ki * 64 + ch * 8);
        }
    };

    uint32_t aOffU = (uint32_t)(wm * 32 + aRow) * 128 + aK16;
    uint32_t bOffU = (uint32_t)(wn * 32 + bRow) * 128 + bK16;

    issue(0, 0); cp_commit();
#pragma unroll 1
    for (int it = 0; it < niter; it++) {
        if (it + 1 < niter) { issue(it + 1, (it + 1) & 1); cp_commit(); cp_wait<1>(); }
        else cp_wait<0>();
        __syncthreads();
        uint32_t bP = sP + (it & 1) * 16384;
        uint32_t bV = sV + (it & 1) * 8192;
#pragma unroll
        for (int slab = 0; slab < 4; slab++) {
            uint32_t a[2][4], bfr[2][4];
            ldsm4(a[0], bP + swz(aOffU + slab * 32));
            ldsm4(a[1], bP + swz(aOffU + 2048 + slab * 32));
            ldsm4(bfr[0], bV + swz(bOffU + slab * 32));
            ldsm4(bfr[1], bV + swz(bOffU + 2048 + slab * 32));
#pragma unroll
            for (int mi = 0; mi < 2; mi++)
#pragma unroll
                for (int nj = 0; nj < 4; nj++)
                    mma16h(acc[mi][nj], a[mi], &bfr[nj >> 1][(nj & 1) * 2]);
        }
        __syncthreads();
    }

#pragma unroll
    for (int mi = 0; mi < 2; mi++) {
        int row = qt * 128 + wm * 32 + mi * 16 + gg;
#pragma unroll
        for (int nj = 0; nj < 4; nj++) {
            int colL = wn * 32 + nj * 8 + 2 * tt;
            __half* d0 = g_Ocat + ((size_t)(b * SEQ) + row) * DMODEL + h * 64 + colL;
            *(__half2*)d0 = __floats2half2_rn(acc[mi][nj][0], acc[mi][nj][1]);
            *(__half2*)(d0 + 8 * DMODEL) = __floats2half2_rn(acc[mi][nj][2], acc[mi][nj][3]);
        }
    }
}

// ---------------------------------------------------------------------------
// Launch. Inputs: keys, queries, values, WQ, WK, WV, WO, masking
// ---------------------------------------------------------------------------
extern "C" void kernel_launch(void* const* d_in, const int* in_sizes, int n_in,
                              void* d_out, int out_size) {
    const float* keys    = (const float*)d_in[0];
    const float* queries = (const float*)d_in[1];
    const float* values  = (const float*)d_in[2];
    const float* WQ      = (const float*)d_in[3];
    const float* WK      = (const float*)d_in[4];
    const float* WV      = (const float*)d_in[5];
    const float* WO      = (const float*)d_in[6];
    float* out = (float*)d_out;
    (void)in_sizes; (void)n_in; (void)out_size;

    const int mmhSmem = 3 * 16384 * 2;                        // 98304
    const int mmvSmem = 3 * 16384 * 2;                        // 98304
    const int denSmem = 8192 + 2 * 16384 + 64 * 65 * 4;       // 57600
    const int pvSmem  = 2 * 16384 + 2 * 8192;                 // 49152
    cudaFuncSetAttribute(mmh_kernel<0>, cudaFuncAttributeMaxDynamicSharedMemorySize, mmhSmem);
    cudaFuncSetAttribute(mmh_kernel<1>, cudaFuncAttributeMaxDynamicSharedMemorySize, mmhSmem);
    cudaFuncSetAttribute(mmv_kernel,    cudaFuncAttributeMaxDynamicSharedMemorySize, mmvSmem);
    cudaFuncSetAttribute(den_kernel,    cudaFuncAttributeMaxDynamicSharedMemorySize, denSmem);
    cudaFuncSetAttribute(pv_kernel,     cudaFuncAttributeMaxDynamicSharedMemorySize, pvSmem);

    // prologue
    xprep_kernel<<<dim3(MROWS * DMODEL / 4 / 256, 1, 3), 256>>>(
        (const float4*)queries, (const float4*)keys, (const float4*)values);
    wprep_kernel<<<dim3(DMODEL / 64, NHEAD, 3), 256>>>(WQ, WK, WV);
    woprep_kernel<<<dim3(DMODEL / 64, DMODEL / 64), 256>>>(WO);

    // projections: Q,K fp16; V tf32
    mmh_kernel<0><<<dim3(MROWS / 128, DMODEL / 128, 2), 256, mmhSmem>>>(nullptr);
    mmv_kernel<<<dim3(MROWS / 128, DMODEL / 128), 256, mmvSmem>>>();

    // attention (fp16)
    den_kernel<<<dim3(SEQ / 64, BH), 256, denSmem>>>();
    pv_kernel<<<dim3(SEQ / 128, BH), 256, pvSmem>>>();

    // output projection (fp16)
    mmh_kernel<1><<<dim3(MROWS / 128, DMODEL / 128, 1), 256, mmhSmem>>>(out);
}

// round 11
// speedup vs baseline: 3.6459x; 1.0280x over previous
#include <cuda_runtime.h>
#include <cuda_fp16.h>
#include <cstdint>
#include <cstddef>

#define BATCH  2
#define SEQ    2048
#define DMODEL 1024
#define NHEAD  16
#define DHEAD  64
#define BH     (BATCH*NHEAD)
#define MROWS  (BATCH*SEQ)
#define SCALE  0.022097086912079608f   // 1/sqrt(2048)

// ---------------- scratch (device globals; allocation-free rule) -----------
__device__ __align__(16) __half g_Xh[(size_t)2 * MROWS * DMODEL];    // fp16 queries/keys
__device__ __align__(16) __half g_Wth[(size_t)2 * DMODEL * DMODEL];  // fp16 n-major WQ/WK
__device__ __align__(16) float  g_Xr[(size_t)MROWS * DMODEL];        // tf32-rounded values
__device__ __align__(16) float  g_Wt[(size_t)DMODEL * DMODEL];       // tf32 n-major WV
__device__ __align__(16) __half g_WOth[(size_t)DMODEL * DMODEL];     // fp16 n-major WO
__device__ __align__(16) __half g_Qh[(size_t)BH * SEQ * DHEAD];
__device__ __align__(16) __half g_Kh[(size_t)BH * SEQ * DHEAD];
__device__ __align__(16) float  g_V[(size_t)BH * SEQ * DHEAD];
__device__ __align__(16) __half g_Vt[(size_t)BH * DHEAD * SEQ];      // [bh][e][k], scaled 1/den
__device__ __align__(16) __half g_Ph[(size_t)BH * SEQ * SEQ];        // exp(scores) fp16
__device__ __align__(16) __half g_Ocat[(size_t)MROWS * DMODEL];      // fp16 attention output

// ---------------- helpers ---------------------------------------------------
__device__ __forceinline__ float rtf(float x) {
    uint32_t u;
    asm("cvt.rna.tf32.f32 %0, %1;" : "=r"(u) : "f"(x));
    return __uint_as_float(u);
}
__device__ __forceinline__ uint32_t swz(uint32_t o) { return o ^ ((o >> 3) & 0x70); }
__device__ __forceinline__ uint32_t smem_u32(const void* p) {
    return (uint32_t)__cvta_generic_to_shared(p);
}
__device__ __forceinline__ void cp16a(uint32_t saddr, const void* gmem) {
    asm volatile("cp.async.cg.shared.global [%0], [%1], 16;" :: "r"(saddr), "l"(gmem));
}
__device__ __forceinline__ void cp_commit() { asm volatile("cp.async.commit_group;"); }
template <int N> __device__ __forceinline__ void cp_wait() {
    asm volatile("cp.async.wait_group %0;" :: "n"(N));
}
__device__ __forceinline__ void ldsm4(uint32_t (&r)[4], uint32_t saddr) {
    asm volatile("ldmatrix.sync.aligned.m8n8.x4.shared.b16 {%0,%1,%2,%3}, [%4];"
                 : "=r"(r[0]), "=r"(r[1]), "=r"(r[2]), "=r"(r[3]) : "r"(saddr));
}
__device__ __forceinline__ void mma8t(float (&c)[4], const uint32_t (&a)[4], const uint32_t* b) {
    asm volatile(
        "mma.sync.aligned.m16n8k8.row.col.f32.tf32.tf32.f32 "
        "{%0,%1,%2,%3}, {%4,%5,%6,%7}, {%8,%9}, {%0,%1,%2,%3};"
        : "+f"(c[0]), "+f"(c[1]), "+f"(c[2]), "+f"(c[3])
        : "r"(a[0]), "r"(a[1]), "r"(a[2]), "r"(a[3]), "r"(b[0]), "r"(b[1]));
}
__device__ __forceinline__ void mma16h(float (&c)[4], const uint32_t (&a)[4], const uint32_t* b) {
    asm volatile(
        "mma.sync.aligned.m16n8k16.row.col.f32.f16.f16.f32 "
        "{%0,%1,%2,%3}, {%4,%5,%6,%7}, {%8,%9}, {%0,%1,%2,%3};"
        : "+f"(c[0]), "+f"(c[1]), "+f"(c[2]), "+f"(c[3])
        : "r"(a[0]), "r"(a[1]), "r"(a[2]), "r"(a[3]), "r"(b[0]), "r"(b[1]));
}
#define LANE_OFFS() \
    int lane = threadIdx.x & 31; \
    int aRow = ((lane >> 3) & 1) * 8 + (lane & 7); \
    int aK16 = (lane >> 4) * 16; \
    int bRow = (lane >> 4) * 8 + (lane & 7); \
    int bK16 = ((lane >> 3) & 1) * 16; \
    int gg = lane >> 2, tt = lane & 3; (void)gg; (void)tt;

// ---------------------------------------------------------------------------
// Prologue: z=0 queries->fp16, z=1 keys->fp16, z=2 values->tf32
// ---------------------------------------------------------------------------
__global__ __launch_bounds__(256) void xprep_kernel(const float4* __restrict__ q,
                                                    const float4* __restrict__ k,
                                                    const float4* __restrict__ v) {
    int which = blockIdx.z;
    const float4* src = (which == 0) ? q : (which == 1) ? k : v;
    size_t i = (size_t)blockIdx.x * 256 + threadIdx.x;
    float4 x = src[i];
    if (which == 2) {
        x.x = rtf(x.x); x.y = rtf(x.y); x.z = rtf(x.z); x.w = rtf(x.w);
        ((float4*)g_Xr)[i] = x;
    } else {
        __half* dst = g_Xh + (size_t)which * MROWS * DMODEL + i * 4;
        *(__half2*)dst = __floats2half2_rn(x.x, x.y);
        *(__half2*)(dst + 2) = __floats2half2_rn(x.z, x.w);
    }
}

// W[h][d][e] -> n-major [h*64+e][d]; z=0 WQ fp16, z=1 WK fp16, z=2 WV tf32
__global__ __launch_bounds__(256) void wprep_kernel(const float* __restrict__ WQ,
                                                    const float* __restrict__ WK,
                                                    const float* __restrict__ WV) {
    int which = blockIdx.z, h = blockIdx.y, d0 = blockIdx.x * 64;
    const float* W = ((which == 0) ? WQ : (which == 1) ? WK : WV)
                     + ((size_t)h * DMODEL + d0) * DHEAD;
    __shared__ float tile[64 * 65];
    int t = threadIdx.x;
#pragma unroll
    for (int j = 0; j < 16; j++) {
        int u = t + j * 256;
        tile[(u >> 6) * 65 + (u & 63)] = W[(size_t)(u >> 6) * DHEAD + (u & 63)];
    }
    __syncthreads();
    if (which == 2) {
        float* out = g_Wt + (size_t)h * 64 * DMODEL + d0;
#pragma unroll
        for (int j = 0; j < 16; j++) {
            int u = t + j * 256;
            int e = u >> 6, dc = u & 63;
            out[(size_t)e * DMODEL + dc] = rtf(tile[dc * 65 + e]);
        }
    } else {
        __half* out = g_Wth + (size_t)which * DMODEL * DMODEL + (size_t)h * 64 * DMODEL + d0;
#pragma unroll
        for (int j = 0; j < 16; j++) {
            int u = t + j * 256;
            int e = u >> 6, dc = u & 63;
            out[(size_t)e * DMODEL + dc] = __float2half_rn(tile[dc * 65 + e]);
        }
    }
}

// WO[d][c] -> fp16 n-major [c][d]
__global__ __launch_bounds__(256) void woprep_kernel(const float* __restrict__ WO) {
    int d0 = blockIdx.x * 64, c0 = blockIdx.y * 64;
    __shared__ float tile[64 * 65];
    int t = threadIdx.x;
#pragma unroll
    for (int j = 0; j < 16; j++) {
        int u = t + j * 256;
        tile[(u >> 6) * 65 + (u & 63)] = WO[(size_t)(d0 + (u >> 6)) * DMODEL + c0 + (u & 63)];
    }
    __syncthreads();
#pragma unroll
    for (int j = 0; j < 16; j++) {
        int u = t + j * 256;
        int cr = u >> 6, dc = u & 63;
        g_WOth[(size_t)(c0 + cr) * DMODEL + d0 + dc] = __float2half_rn(tile[dc * 65 + cr]);
    }
}

// ---------------------------------------------------------------------------
// proj_kernel: ALL three projections in one launch for wave packing.
// z=0/1: fp16 (BK=64, 16 iters) -> g_Qh/g_Kh; z=2: tf32 (BK=32, 32 iters) -> g_V.
// 3-stage cp.async, prefetch distance 2, ONE __syncthreads per iteration
// (issue happens after compute; stage being written was last read pre-sync).
// ---------------------------------------------------------------------------
__global__ __launch_bounds__(256, 2) void proj_kernel() {
    extern __shared__ float smf[];
    uint32_t sA = smem_u32(smf);           // [3][128 x 128B] = 48KB
    uint32_t sB = sA + 3 * 16384;          // [3][128 x 128B] = 48KB

    int t = threadIdx.x, wid = t >> 5;
    int wm = wid & 1, wn = wid >> 1;       // 2x4 warps -> 128x128, warp 64x32
    int m0 = blockIdx.x * 128, n0 = blockIdx.y * 128, which = blockIdx.z;
    LANE_OFFS();

    uint32_t aOffU = (uint32_t)(wm * 64 + aRow) * 128 + aK16;
    uint32_t bOffU = (uint32_t)(wn * 32 + bRow) * 128 + bK16;

    float acc[4][4][4];
#pragma unroll
    for (int mi = 0; mi < 4; mi++)
#pragma unroll
        for (int nj = 0; nj < 4; nj++)
#pragma unroll
            for (int e = 0; e < 4; e++) acc[mi][nj][e] = 0.0f;

    if (which < 2) {
        // ---------- fp16 Q/K projection ----------
        const __half* A = g_Xh + (size_t)which * MROWS * DMODEL + (size_t)m0 * DMODEL;
        const __half* B = g_Wth + (size_t)which * DMODEL * DMODEL + (size_t)n0 * DMODEL;

        auto issue = [&](int it3) {
            int s = it3 % 3;
            int kk = it3 * 64;
            uint32_t bA = sA + s * 16384;
            uint32_t bB = sB + s * 16384;
#pragma unroll
            for (int j = 0; j < 4; j++) {
                int u = t + j * 256;
                int row = u >> 3, ch = u & 7;
                uint32_t off = swz(row * 128 + ch * 16);
                cp16a(bA + off, A + (size_t)row * DMODEL + kk + ch * 8);
                cp16a(bB + off, B + (size_t)row * DMODEL + kk + ch * 8);
            }
        };

        issue(0); cp_commit();
        issue(1); cp_commit();
#pragma unroll 1
        for (int it = 0; it < 16; it++) {
            if (it < 15) cp_wait<1>(); else cp_wait<0>();
            __syncthreads();
            uint32_t bA = sA + (it % 3) * 16384;
            uint32_t bB = sB + (it % 3) * 16384;
#pragma unroll
            for (int slab = 0; slab < 4; slab++) {
                uint32_t a[4][4], b[2][4];
#pragma unroll
                for (int mi = 0; mi < 4; mi++)
                    ldsm4(a[mi], bA + swz(aOffU + mi * 2048 + slab * 32));
#pragma unroll
                for (int g2 = 0; g2 < 2; g2++)
                    ldsm4(b[g2], bB + swz(bOffU + g2 * 2048 + slab * 32));
#pragma unroll
                for (int mi = 0; mi < 4; mi++)
#pragma unroll
                    for (int nj = 0; nj < 4; nj++)
                        mma16h(acc[mi][nj], a[mi], &b[nj >> 1][(nj & 1) * 2]);
            }
            if (it + 2 < 16) { issue(it + 2); cp_commit(); }
        }

#pragma unroll
        for (int mi = 0; mi < 4; mi++) {
            int mrow = m0 + wm * 64 + mi * 16 + gg;
#pragma unroll
            for (int nj = 0; nj < 4; nj++) {
                int col = n0 + wn * 32 + nj * 8 + 2 * tt;
                int b = mrow >> 11, s = mrow & (SEQ - 1);
                int h = col >> 6, e = col & 63;
                __half* dst = ((which == 0) ? g_Qh : g_Kh)
                              + ((size_t)(b * NHEAD + h) * SEQ + s) * DHEAD + e;
                *(__half2*)dst = __floats2half2_rn(acc[mi][nj][0], acc[mi][nj][1]);
                *(__half2*)(dst + 8 * DHEAD) = __floats2half2_rn(acc[mi][nj][2], acc[mi][nj][3]);
            }
        }
    } else {
        // ---------- tf32 V projection ----------
        const float* A = g_Xr + (size_t)m0 * DMODEL;
        const float* B = g_Wt + (size_t)n0 * DMODEL;

        auto issue = [&](int it3) {
            int s = it3 % 3;
            int kk = it3 * 32;
            uint32_t bA = sA + s * 16384;
            uint32_t bB = sB + s * 16384;
#pragma unroll
            for (int j = 0; j < 4; j++) {
                int u = t + j * 256;
                int row = u >> 3, at = u & 7;
                uint32_t off = swz(row * 128 + at * 16);
                cp16a(bA + off, A + (size_t)row * DMODEL + kk + at * 4);
                cp16a(bB + off, B + (size_t)row * DMODEL + kk + at * 4);
            }
        };

        issue(0); cp_commit();
        issue(1); cp_commit();
#pragma unroll 1
        for (int it = 0; it < 32; it++) {
            if (it < 31) cp_wait<1>(); else cp_wait<0>();
            __syncthreads();
            uint32_t bA = sA + (it % 3) * 16384;
            uint32_t bB = sB + (it % 3) * 16384;
#pragma unroll
            for (int slab = 0; slab < 4; slab++) {
                uint32_t a[4][4], b[2][4];
#pragma unroll
                for (int mi = 0; mi < 4; mi++)
                    ldsm4(a[mi], bA + swz(aOffU + mi * 2048 + slab * 32));
#pragma unroll
                for (int g2 = 0; g2 < 2; g2++)
                    ldsm4(b[g2], bB + swz(bOffU + g2 * 2048 + slab * 32));
#pragma unroll
                for (int mi = 0; mi < 4; mi++)
#pragma unroll
                    for (int nj = 0; nj < 4; nj++)
                        mma8t(acc[mi][nj], a[mi], &b[nj >> 1][(nj & 1) * 2]);
            }
            if (it + 2 < 32) { issue(it + 2); cp_commit(); }
        }

#pragma unroll
        for (int mi = 0; mi < 4; mi++) {
            int mrow = m0 + wm * 64 + mi * 16 + gg;
#pragma unroll
            for (int nj = 0; nj < 4; nj++) {
                int col = n0 + wn * 32 + nj * 8 + 2 * tt;
                int b = mrow >> 11, s = mrow & (SEQ - 1);
                int h = col >> 6, e = col & 63;
                size_t off = ((size_t)(b * NHEAD + h) * SEQ + s) * DHEAD + e;
                *(float2*)&g_V[off] = make_float2(acc[mi][nj][0], acc[mi][nj][1]);
                *(float2*)&g_V[off + 8 * DHEAD] = make_float2(acc[mi][nj][2], acc[mi][nj][3]);
            }
        }
    }
}

// ---------------------------------------------------------------------------
// out_kernel (fp16, BK=64, 3-stage, single-sync): Out = Ocat @ WOt^T -> fp32.
// ---------------------------------------------------------------------------
__global__ __launch_bounds__(256, 2) void out_kernel(float* __restrict__ Cout) {
    extern __shared__ float smf[];
    uint32_t sA = smem_u32(smf);
    uint32_t sB = sA + 3 * 16384;

    int t = threadIdx.x, wid = t >> 5;
    int wm = wid & 1, wn = wid >> 1;
    int m0 = blockIdx.x * 128, n0 = blockIdx.y * 128;
    LANE_OFFS();

    const __half* A = g_Ocat + (size_t)m0 * DMODEL;
    const __half* B = g_WOth + (size_t)n0 * DMODEL;

    float acc[4][4][4];
#pragma unroll
    for (int mi = 0; mi < 4; mi++)
#pragma unroll
        for (int nj = 0; nj < 4; nj++)
#pragma unroll
            for (int e = 0; e < 4; e++) acc[mi][nj][e] = 0.0f;

    auto issue = [&](int it3) {
        int s = it3 % 3;
        int kk = it3 * 64;
        uint32_t bA = sA + s * 16384;
        uint32_t bB = sB + s * 16384;
#pragma unroll
        for (int j = 0; j < 4; j++) {
            int u = t + j * 256;
            int row = u >> 3, ch = u & 7;
            uint32_t off = swz(row * 128 + ch * 16);
            cp16a(bA + off, A + (size_t)row * DMODEL + kk + ch * 8);
            cp16a(bB + off, B + (size_t)row * DMODEL + kk + ch * 8);
        }
    };

    uint32_t aOffU = (uint32_t)(wm * 64 + aRow) * 128 + aK16;
    uint32_t bOffU = (uint32_t)(wn * 32 + bRow) * 128 + bK16;

    issue(0); cp_commit();
    issue(1); cp_commit();
#pragma unroll 1
    for (int it = 0; it < 16; it++) {
        if (it < 15) cp_wait<1>(); else cp_wait<0>();
        __syncthreads();
        uint32_t bA = sA + (it % 3) * 16384;
        uint32_t bB = sB + (it % 3) * 16384;
#pragma unroll
        for (int slab = 0; slab < 4; slab++) {
            uint32_t a[4][4], b[2][4];
#pragma unroll
            for (int mi = 0; mi < 4; mi++)
                ldsm4(a[mi], bA + swz(aOffU + mi * 2048 + slab * 32));
#pragma unroll
            for (int g2 = 0; g2 < 2; g2++)
                ldsm4(b[g2], bB + swz(bOffU + g2 * 2048 + slab * 32));
#pragma unroll
            for (int mi = 0; mi < 4; mi++)
#pragma unroll
                for (int nj = 0; nj < 4; nj++)
                    mma16h(acc[mi][nj], a[mi], &b[nj >> 1][(nj & 1) * 2]);
        }
        if (it + 2 < 16) { issue(it + 2); cp_commit(); }
    }

#pragma unroll
    for (int mi = 0; mi < 4; mi++) {
        int mrow = m0 + wm * 64 + mi * 16 + gg;
#pragma unroll
        for (int nj = 0; nj < 4; nj++) {
            int col = n0 + wn * 32 + nj * 8 + 2 * tt;
            float* d0 = Cout + (size_t)mrow * DMODEL + col;
            *(float2*)d0 = make_float2(acc[mi][nj][0], acc[mi][nj][1]);
            *(float2*)(d0 + 8 * DMODEL) = make_float2(acc[mi][nj][2], acc[mi][nj][3]);
        }
    }
}

// ---------------------------------------------------------------------------
// den_kernel (fp16 scores): unchanged structure (already single-sync).
// ---------------------------------------------------------------------------
__global__ __launch_bounds__(256, 2) void den_kernel() {
    int kt = blockIdx.x;
    int bh = blockIdx.y;

    extern __shared__ float smf[];
    uint32_t sK = smem_u32(smf);                 // fp16 K stripe: 8KB
    uint32_t sQ = sK + 8192;                     // fp16 Q tiles: 2 x 16KB
    float* Vstage = (float*)((char*)smf + 8192 + 32768);  // [64][65] fp32
    __shared__ float colsum[4][64];
    __shared__ float invs[64];

    int t = threadIdx.x, wid = t >> 5;
    int wm = wid & 3, wn = wid >> 2;             // 4x2 warps -> 128q x 64k
    LANE_OFFS();

    const __half* Qg = g_Qh + (size_t)bh * SEQ * DHEAD;
    const __half* Kg = g_Kh + ((size_t)bh * SEQ + kt * 64) * DHEAD;
    __half* Pb = g_Ph + (size_t)bh * SEQ * SEQ + kt * 64;

    auto issueQ = [&](int qt, int s) {
        const __half* src = Qg + (size_t)qt * 128 * DHEAD;
        uint32_t base = sQ + s * 16384;
#pragma unroll
        for (int j = 0; j < 4; j++) {
            int u = t + j * 256;
            int row = u >> 3, ch = u & 7;
            cp16a(base + swz(row * 128 + ch * 16), src + (size_t)row * DHEAD + ch * 8);
        }
    };

#pragma unroll
    for (int j = 0; j < 2; j++) {
        int u = t + j * 256;
        int row = u >> 3, ch = u & 7;
        cp16a(sK + swz(row * 128 + ch * 16), Kg + (size_t)row * DHEAD + ch * 8);
    }
    int qt0 = kt >> 1;
    issueQ(qt0, 0); cp_commit(); cp_wait<0>(); __syncthreads();

    uint32_t aOffU = (uint32_t)(wm * 32 + aRow) * 128 + aK16;
    uint32_t bOffU = (uint32_t)(wn * 32 + bRow) * 128 + bK16;

    float part[4][2];
#pragma unroll
    for (int nj = 0; nj < 4; nj++) { part[nj][0] = 0.0f; part[nj][1] = 0.0f; }

#pragma unroll 1
    for (int qt = qt0; qt < SEQ / 128; qt++) {
        int it = qt - qt0;
        if (qt + 1 < SEQ / 128) { issueQ(qt + 1, (it + 1) & 1); cp_commit(); }

        uint32_t baQ = sQ + (it & 1) * 16384;
        float acc[2][4][4];
#pragma unroll
        for (int mi = 0; mi < 2; mi++)
#pragma unroll
            for (int nj = 0; nj < 4; nj++)
#pragma unroll
                for (int e = 0; e < 4; e++) acc[mi][nj][e] = 0.0f;

#pragma unroll
        for (int slab = 0; slab < 4; slab++) {
            uint32_t a[2][4], b[2][4];
            ldsm4(a[0], baQ + swz(aOffU + slab * 32));
            ldsm4(a[1], baQ + swz(aOffU + 2048 + slab * 32));
            ldsm4(b[0], sK + swz(bOffU + slab * 32));
            ldsm4(b[1], sK + swz(bOffU + 2048 + slab * 32));
#pragma unroll
            for (int mi = 0; mi < 2; mi++)
#pragma unroll
                for (int nj = 0; nj < 4; nj++)
                    mma16h(acc[mi][nj], a[mi], &b[nj >> 1][(nj & 1) * 2]);
        }

        int q0 = qt * 128;
#pragma unroll
        for (int mi = 0; mi < 2; mi++) {
            int row = wm * 32 + mi * 16 + gg;
            int q = q0 + row;
#pragma unroll
            for (int nj = 0; nj < 4; nj++) {
                int kl = wn * 32 + nj * 8 + 2 * tt;
                int kg = kt * 64 + kl;
                float v0 = (kg     <= q) ? __expf((acc[mi][nj][0] + (float)(kg - q)) * SCALE) : 0.0f;
                float v1 = (kg + 1 <= q) ? __expf((acc[mi][nj][1] + (float)(kg + 1 - q)) * SCALE) : 0.0f;
                float v2 = (kg     <= q + 8) ? __expf((acc[mi][nj][2] + (float)(kg - q - 8)) * SCALE) : 0.0f;
                float v3 = (kg + 1 <= q + 8) ? __expf((acc[mi][nj][3] + (float)(kg + 1 - q - 8)) * SCALE) : 0.0f;
                part[nj][0] += v0 + v2;
                part[nj][1] += v1 + v3;
                *(__half2*)&Pb[(size_t)q * SEQ + kl] = __floats2half2_rn(v0, v1);
                *(__half2*)&Pb[(size_t)(q + 8) * SEQ + kl] = __floats2half2_rn(v2, v3);
            }
        }
        cp_wait<0>(); __syncthreads();
    }

#pragma unroll
    for (int nj = 0; nj < 4; nj++)
#pragma unroll
        for (int p = 0; p < 2; p++) {
            float v = part[nj][p];
            v += __shfl_xor_sync(0xffffffffu, v, 4);
            v += __shfl_xor_sync(0xffffffffu, v, 8);
            v += __shfl_xor_sync(0xffffffffu, v, 16);
            part[nj][p] = v;
        }
    if (lane < 4) {
#pragma unroll
        for (int nj = 0; nj < 4; nj++) {
            colsum[wm][wn * 32 + nj * 8 + 2 * lane]     = part[nj][0];
            colsum[wm][wn * 32 + nj * 8 + 2 * lane + 1] = part[nj][1];
        }
    }
    __syncthreads();
    if (t < 64)
        invs[t] = 1.0f / (colsum[0][t] + colsum[1][t] + colsum[2][t] + colsum[3][t]);
    __syncthreads();

    const float* Vg = g_V + ((size_t)bh * SEQ + kt * 64) * DHEAD;
#pragma unroll
    for (int j = 0; j < 4; j++) {
        int u = t + j * 256;
        int r = u >> 4, e4 = (u & 15) * 4;
        float4 v = *(const float4*)&Vg[(size_t)r * DHEAD + e4];
        float iv = invs[r];
        Vstage[r * 65 + e4 + 0] = v.x * iv;
        Vstage[r * 65 + e4 + 1] = v.y * iv;
        Vstage[r * 65 + e4 + 2] = v.z * iv;
        Vstage[r * 65 + e4 + 3] = v.w * iv;
    }
    __syncthreads();
    __half* Vt = g_Vt + (size_t)bh * DHEAD * SEQ + kt * 64;
#pragma unroll
    for (int er = 0; er < 8; er++) {
        int e = wid * 8 + er;
#pragma unroll
        for (int half_ = 0; half_ < 2; half_++) {
            int r = lane + half_ * 32;
            Vt[(size_t)e * SEQ + r] = __float2half_rn(Vstage[r * 65 + e]);
        }
    }
}

// ---------------------------------------------------------------------------
// pv_kernel (fp16): Ocat[128q x 64e] = P @ Vt^T, BK=64, 3-stage single-sync.
// ---------------------------------------------------------------------------
__global__ __launch_bounds__(256, 2) void pv_kernel() {
    int qt = (int)gridDim.x - 1 - blockIdx.x;
    int bh = blockIdx.y;
    int b = bh >> 4, h = bh & 15;

    extern __shared__ float smf[];
    uint32_t sP = smem_u32(smf);                 // [3][128 x 128B] = 48KB
    uint32_t sV = sP + 3 * 16384;                // [3][64 x 128B]  = 24KB

    int t = threadIdx.x, wid = t >> 5;
    int wm = wid & 3, wn = wid >> 2;
    LANE_OFFS();

    const __half* Pg = g_Ph + ((size_t)bh * SEQ + qt * 128) * SEQ;
    const __half* Vtg = g_Vt + (size_t)bh * DHEAD * SEQ;

    float acc[2][4][4];
#pragma unroll
    for (int mi = 0; mi < 2; mi++)
#pragma unroll
        for (int nj = 0; nj < 4; nj++)
#pragma unroll
            for (int e = 0; e < 4; e++) acc[mi][nj][e] = 0.0f;

    int niter = 2 * qt + 2;

    auto issue = [&](int it3) {
        int s = it3 % 3;
        uint32_t bP = sP + s * 16384;
#pragma unroll
        for (int j = 0; j < 4; j++) {
            int u = t + j * 256;
            int row = u >> 3, ch = u & 7;
            cp16a(bP + swz(row * 128 + ch * 16), Pg + (size_t)row * SEQ + it3 * 64 + ch * 8);
        }
        uint32_t bV = sV + s * 8192;
#pragma unroll
        for (int j = 0; j < 2; j++) {
            int u = t + j * 256;
            int row = u >> 3, ch = u & 7;
            cp16a(bV + swz(row * 128 + ch * 16), Vtg + (size_t)row * SEQ + it3 * 64 + ch * 8);
        }
    };

    uint32_t aOffU = (uint32_t)(wm * 32 + aRow) * 128 + aK16;
    uint32_t bOffU = (uint32_t)(wn * 32 + bRow) * 128 + bK16;

    issue(0); cp_commit();
    if (niter > 1) { issue(1); cp_commit(); }
#pragma unroll 1
    for (int it = 0; it < niter; it++) {
        if (it + 1 < niter) cp_wait<1>(); else cp_wait<0>();
        __syncthreads();
        uint32_t bP = sP + (it % 3) * 16384;
        uint32_t bV = sV + (it % 3) * 8192;
#pragma unroll
        for (int slab = 0; slab < 4; slab++) {
            uint32_t a[2][4], bfr[2][4];
            ldsm4(a[0], bP + swz(aOffU + slab * 32));
            ldsm4(a[1], bP + swz(aOffU + 2048 + slab * 32));
            ldsm4(bfr[0], bV + swz(bOffU + slab * 32));
            ldsm4(bfr[1], bV + swz(bOffU + 2048 + slab * 32));
#pragma unroll
            for (int mi = 0; mi < 2; mi++)
#pragma unroll
                for (int nj = 0; nj < 4; nj++)
                    mma16h(acc[mi][nj], a[mi], &bfr[nj >> 1][(nj & 1) * 2]);
        }
        if (it + 2 < niter) { issue(it + 2); cp_commit(); }
    }

#pragma unroll
    for (int mi = 0; mi < 2; mi++) {
        int row = qt * 128 + wm * 32 + mi * 16 + gg;
#pragma unroll
        for (int nj = 0; nj < 4; nj++) {
            int colL = wn * 32 + nj * 8 + 2 * tt;
            __half* d0 = g_Ocat + ((size_t)(b * SEQ) + row) * DMODEL + h * 64 + colL;
            *(__half2*)d0 = __floats2half2_rn(acc[mi][nj][0], acc[mi][nj][1]);
            *(__half2*)(d0 + 8 * DMODEL) = __floats2half2_rn(acc[mi][nj][2], acc[mi][nj][3]);
        }
    }
}

// ---------------------------------------------------------------------------
// Launch. Inputs: keys, queries, values, WQ, WK, WV, WO, masking
// ---------------------------------------------------------------------------
extern "C" void kernel_launch(void* const* d_in, const int* in_sizes, int n_in,
                              void* d_out, int out_size) {
    const float* keys    = (const float*)d_in[0];
    const float* queries = (const float*)d_in[1];
    const float* values  = (const float*)d_in[2];
    const float* WQ      = (const float*)d_in[3];
    const float* WK      = (const float*)d_in[4];
    const float* WV      = (const float*)d_in[5];
    const float* WO      = (const float*)d_in[6];
    float* out = (float*)d_out;
    (void)in_sizes; (void)n_in; (void)out_size;

    const int projSmem = 3 * 16384 * 2;                       // 98304
    const int outSmem  = 3 * 16384 * 2;                       // 98304
    const int denSmem  = 8192 + 2 * 16384 + 64 * 65 * 4;      // 57600
    const int pvSmem   = 3 * 16384 + 3 * 8192;                // 73728
    cudaFuncSetAttribute(proj_kernel, cudaFuncAttributeMaxDynamicSharedMemorySize, projSmem);
    cudaFuncSetAttribute(out_kernel,  cudaFuncAttributeMaxDynamicSharedMemorySize, outSmem);
    cudaFuncSetAttribute(den_kernel,  cudaFuncAttributeMaxDynamicSharedMemorySize, denSmem);
    cudaFuncSetAttribute(pv_kernel,   cudaFuncAttributeMaxDynamicSharedMemorySize, pvSmem);

    // prologue
    xprep_kernel<<<dim3(MROWS * DMODEL / 4 / 256, 1, 3), 256>>>(
        (const float4*)queries, (const float4*)keys, (const float4*)values);
    wprep_kernel<<<dim3(DMODEL / 64, NHEAD, 3), 256>>>(WQ, WK, WV);
    woprep_kernel<<<dim3(DMODEL / 64, DMODEL / 64), 256>>>(WO);

    // all projections in one launch (z=0 Q fp16, z=1 K fp16, z=2 V tf32)
    proj_kernel<<<dim3(MROWS / 128, DMODEL / 128, 3), 256, projSmem>>>();

    // attention (fp16)
    den_kernel<<<dim3(SEQ / 64, BH), 256, denSmem>>>();
    pv_kernel<<<dim3(SEQ / 128, BH), 256, pvSmem>>>();

    // output projection (fp16)
    out_kernel<<<dim3(MROWS / 128, DMODEL / 128), 256, outSmem>>>(out);
}

// round 12
// speedup vs baseline: 3.9523x; 1.0840x over previous
#include <cuda_runtime.h>
#include <cuda_fp16.h>
#include <cstdint>
#include <cstddef>

#define BATCH  2
#define SEQ    2048
#define DMODEL 1024
#define NHEAD  16
#define DHEAD  64
#define BH     (BATCH*NHEAD)
#define MROWS  (BATCH*SEQ)
#define SCALE  0.022097086912079608f   // 1/sqrt(2048)

// ---------------- scratch (device globals; allocation-free rule) -----------
__device__ __align__(16) __half g_Xh[(size_t)3 * MROWS * DMODEL];    // fp16 q/k/v inputs
__device__ __align__(16) __half g_Wth[(size_t)3 * DMODEL * DMODEL];  // fp16 n-major WQ/WK/WV
__device__ __align__(16) __half g_WOth[(size_t)DMODEL * DMODEL];     // fp16 n-major WO
__device__ __align__(16) __half g_Qh[(size_t)BH * SEQ * DHEAD];
__device__ __align__(16) __half g_Kh[(size_t)BH * SEQ * DHEAD];
__device__ __align__(16) __half g_Vh[(size_t)BH * SEQ * DHEAD];
__device__ __align__(16) __half g_Vt[(size_t)BH * DHEAD * SEQ];      // [bh][e][k], scaled 1/den
__device__ __align__(16) __half g_Ph[(size_t)BH * SEQ * SEQ];        // exp(scores) fp16
__device__ __align__(16) __half g_Ocat[(size_t)MROWS * DMODEL];      // fp16 attention output

// ---------------- helpers ---------------------------------------------------
__device__ __forceinline__ uint32_t swz(uint32_t o) { return o ^ ((o >> 3) & 0x70); }
__device__ __forceinline__ uint32_t smem_u32(const void* p) {
    return (uint32_t)__cvta_generic_to_shared(p);
}
__device__ __forceinline__ void cp16a(uint32_t saddr, const void* gmem) {
    asm volatile("cp.async.cg.shared.global [%0], [%1], 16;" :: "r"(saddr), "l"(gmem));
}
__device__ __forceinline__ void cp_commit() { asm volatile("cp.async.commit_group;"); }
template <int N> __device__ __forceinline__ void cp_wait() {
    asm volatile("cp.async.wait_group %0;" :: "n"(N));
}
__device__ __forceinline__ void ldsm4(uint32_t (&r)[4], uint32_t saddr) {
    asm volatile("ldmatrix.sync.aligned.m8n8.x4.shared.b16 {%0,%1,%2,%3}, [%4];"
                 : "=r"(r[0]), "=r"(r[1]), "=r"(r[2]), "=r"(r[3]) : "r"(saddr));
}
__device__ __forceinline__ void mma16h(float (&c)[4], const uint32_t (&a)[4], const uint32_t* b) {
    asm volatile(
        "mma.sync.aligned.m16n8k16.row.col.f32.f16.f16.f32 "
        "{%0,%1,%2,%3}, {%4,%5,%6,%7}, {%8,%9}, {%0,%1,%2,%3};"
        : "+f"(c[0]), "+f"(c[1]), "+f"(c[2]), "+f"(c[3])
        : "r"(a[0]), "r"(a[1]), "r"(a[2]), "r"(a[3]), "r"(b[0]), "r"(b[1]));
}
#define LANE_OFFS() \
    int lane = threadIdx.x & 31; \
    int aRow = ((lane >> 3) & 1) * 8 + (lane & 7); \
    int aK16 = (lane >> 4) * 16; \
    int bRow = (lane >> 4) * 8 + (lane & 7); \
    int bK16 = ((lane >> 3) & 1) * 16; \
    int gg = lane >> 2, tt = lane & 3; (void)gg; (void)tt;

// ---------------------------------------------------------------------------
// Prologue: queries/keys/values -> fp16
// ---------------------------------------------------------------------------
__global__ __launch_bounds__(256) void xprep_kernel(const float4* __restrict__ q,
                                                    const float4* __restrict__ k,
                                                    const float4* __restrict__ v) {
    int which = blockIdx.z;
    const float4* src = (which == 0) ? q : (which == 1) ? k : v;
    size_t i = (size_t)blockIdx.x * 256 + threadIdx.x;
    float4 x = src[i];
    __half* dst = g_Xh + (size_t)which * MROWS * DMODEL + i * 4;
    *(__half2*)dst = __floats2half2_rn(x.x, x.y);
    *(__half2*)(dst + 2) = __floats2half2_rn(x.z, x.w);
}

// W[h][d][e] -> fp16 n-major [h*64+e][d] for WQ/WK/WV
__global__ __launch_bounds__(256) void wprep_kernel(const float* __restrict__ WQ,
                                                    const float* __restrict__ WK,
                                                    const float* __restrict__ WV) {
    int which = blockIdx.z, h = blockIdx.y, d0 = blockIdx.x * 64;
    const float* W = ((which == 0) ? WQ : (which == 1) ? WK : WV)
                     + ((size_t)h * DMODEL + d0) * DHEAD;
    __shared__ float tile[64 * 65];
    int t = threadIdx.x;
#pragma unroll
    for (int j = 0; j < 16; j++) {
        int u = t + j * 256;
        tile[(u >> 6) * 65 + (u & 63)] = W[(size_t)(u >> 6) * DHEAD + (u & 63)];
    }
    __syncthreads();
    __half* out = g_Wth + (size_t)which * DMODEL * DMODEL + (size_t)h * 64 * DMODEL + d0;
#pragma unroll
    for (int j = 0; j < 16; j++) {
        int u = t + j * 256;
        int e = u >> 6, dc = u & 63;
        out[(size_t)e * DMODEL + dc] = __float2half_rn(tile[dc * 65 + e]);
    }
}

// WO[d][c] -> fp16 n-major [c][d]
__global__ __launch_bounds__(256) void woprep_kernel(const float* __restrict__ WO) {
    int d0 = blockIdx.x * 64, c0 = blockIdx.y * 64;
    __shared__ float tile[64 * 65];
    int t = threadIdx.x;
#pragma unroll
    for (int j = 0; j < 16; j++) {
        int u = t + j * 256;
        tile[(u >> 6) * 65 + (u & 63)] = WO[(size_t)(d0 + (u >> 6)) * DMODEL + c0 + (u & 63)];
    }
    __syncthreads();
#pragma unroll
    for (int j = 0; j < 16; j++) {
        int u = t + j * 256;
        int cr = u >> 6, dc = u & 63;
        g_WOth[(size_t)(c0 + cr) * DMODEL + d0 + dc] = __float2half_rn(tile[dc * 65 + cr]);
    }
}

// ---------------------------------------------------------------------------
// proj_kernel: ALL three projections, uniform fp16 (BK=64, 16 iters, 3-stage,
// prefetch distance 2, one __syncthreads per iteration).
// z=0 -> g_Qh, z=1 -> g_Kh, z=2 -> g_Vh.
// ---------------------------------------------------------------------------
__global__ __launch_bounds__(256, 2) void proj_kernel() {
    extern __shared__ float smf[];
    uint32_t sA = smem_u32(smf);           // [3][128 x 128B] = 48KB
    uint32_t sB = sA + 3 * 16384;          // [3][128 x 128B] = 48KB

    int t = threadIdx.x, wid = t >> 5;
    int wm = wid & 1, wn = wid >> 1;       // 2x4 warps -> 128x128, warp 64x32
    int m0 = blockIdx.x * 128, n0 = blockIdx.y * 128, which = blockIdx.z;
    LANE_OFFS();

    const __half* A = g_Xh + (size_t)which * MROWS * DMODEL + (size_t)m0 * DMODEL;
    const __half* B = g_Wth + (size_t)which * DMODEL * DMODEL + (size_t)n0 * DMODEL;

    uint32_t aOffU = (uint32_t)(wm * 64 + aRow) * 128 + aK16;
    uint32_t bOffU = (uint32_t)(wn * 32 + bRow) * 128 + bK16;

    float acc[4][4][4];
#pragma unroll
    for (int mi = 0; mi < 4; mi++)
#pragma unroll
        for (int nj = 0; nj < 4; nj++)
#pragma unroll
            for (int e = 0; e < 4; e++) acc[mi][nj][e] = 0.0f;

    auto issue = [&](int it3) {
        int s = it3 % 3;
        int kk = it3 * 64;
        uint32_t bA = sA + s * 16384;
        uint32_t bB = sB + s * 16384;
#pragma unroll
        for (int j = 0; j < 4; j++) {
            int u = t + j * 256;
            int row = u >> 3, ch = u & 7;
            uint32_t off = swz(row * 128 + ch * 16);
            cp16a(bA + off, A + (size_t)row * DMODEL + kk + ch * 8);
            cp16a(bB + off, B + (size_t)row * DMODEL + kk + ch * 8);
        }
    };

    issue(0); cp_commit();
    issue(1); cp_commit();
#pragma unroll 1
    for (int it = 0; it < 16; it++) {
        if (it < 15) cp_wait<1>(); else cp_wait<0>();
        __syncthreads();
        uint32_t bA = sA + (it % 3) * 16384;
        uint32_t bB = sB + (it % 3) * 16384;
#pragma unroll
        for (int slab = 0; slab < 4; slab++) {
            uint32_t a[4][4], b[2][4];
#pragma unroll
            for (int mi = 0; mi < 4; mi++)
                ldsm4(a[mi], bA + swz(aOffU + mi * 2048 + slab * 32));
#pragma unroll
            for (int g2 = 0; g2 < 2; g2++)
                ldsm4(b[g2], bB + swz(bOffU + g2 * 2048 + slab * 32));
#pragma unroll
            for (int mi = 0; mi < 4; mi++)
#pragma unroll
                for (int nj = 0; nj < 4; nj++)
                    mma16h(acc[mi][nj], a[mi], &b[nj >> 1][(nj & 1) * 2]);
        }
        if (it + 2 < 16) { issue(it + 2); cp_commit(); }
    }

    __half* Outp = (which == 0) ? g_Qh : (which == 1) ? g_Kh : g_Vh;
#pragma unroll
    for (int mi = 0; mi < 4; mi++) {
        int mrow = m0 + wm * 64 + mi * 16 + gg;
#pragma unroll
        for (int nj = 0; nj < 4; nj++) {
            int col = n0 + wn * 32 + nj * 8 + 2 * tt;
            int b = mrow >> 11, s = mrow & (SEQ - 1);
            int h = col >> 6, e = col & 63;
            __half* dst = Outp + ((size_t)(b * NHEAD + h) * SEQ + s) * DHEAD + e;
            *(__half2*)dst = __floats2half2_rn(acc[mi][nj][0], acc[mi][nj][1]);
            *(__half2*)(dst + 8 * DHEAD) = __floats2half2_rn(acc[mi][nj][2], acc[mi][nj][3]);
        }
    }
}

// ---------------------------------------------------------------------------
// out_kernel (fp16, BK=64, 3-stage, single-sync): Out = Ocat @ WOt^T -> fp32.
// ---------------------------------------------------------------------------
__global__ __launch_bounds__(256, 2) void out_kernel(float* __restrict__ Cout) {
    extern __shared__ float smf[];
    uint32_t sA = smem_u32(smf);
    uint32_t sB = sA + 3 * 16384;

    int t = threadIdx.x, wid = t >> 5;
    int wm = wid & 1, wn = wid >> 1;
    int m0 = blockIdx.x * 128, n0 = blockIdx.y * 128;
    LANE_OFFS();

    const __half* A = g_Ocat + (size_t)m0 * DMODEL;
    const __half* B = g_WOth + (size_t)n0 * DMODEL;

    float acc[4][4][4];
#pragma unroll
    for (int mi = 0; mi < 4; mi++)
#pragma unroll
        for (int nj = 0; nj < 4; nj++)
#pragma unroll
            for (int e = 0; e < 4; e++) acc[mi][nj][e] = 0.0f;

    auto issue = [&](int it3) {
        int s = it3 % 3;
        int kk = it3 * 64;
        uint32_t bA = sA + s * 16384;
        uint32_t bB = sB + s * 16384;
#pragma unroll
        for (int j = 0; j < 4; j++) {
            int u = t + j * 256;
            int row = u >> 3, ch = u & 7;
            uint32_t off = swz(row * 128 + ch * 16);
            cp16a(bA + off, A + (size_t)row * DMODEL + kk + ch * 8);
            cp16a(bB + off, B + (size_t)row * DMODEL + kk + ch * 8);
        }
    };

    uint32_t aOffU = (uint32_t)(wm * 64 + aRow) * 128 + aK16;
    uint32_t bOffU = (uint32_t)(wn * 32 + bRow) * 128 + bK16;

    issue(0); cp_commit();
    issue(1); cp_commit();
#pragma unroll 1
    for (int it = 0; it < 16; it++) {
        if (it < 15) cp_wait<1>(); else cp_wait<0>();
        __syncthreads();
        uint32_t bA = sA + (it % 3) * 16384;
        uint32_t bB = sB + (it % 3) * 16384;
#pragma unroll
        for (int slab = 0; slab < 4; slab++) {
            uint32_t a[4][4], b[2][4];
#pragma unroll
            for (int mi = 0; mi < 4; mi++)
                ldsm4(a[mi], bA + swz(aOffU + mi * 2048 + slab * 32));
#pragma unroll
            for (int g2 = 0; g2 < 2; g2++)
                ldsm4(b[g2], bB + swz(bOffU + g2 * 2048 + slab * 32));
#pragma unroll
            for (int mi = 0; mi < 4; mi++)
#pragma unroll
                for (int nj = 0; nj < 4; nj++)
                    mma16h(acc[mi][nj], a[mi], &b[nj >> 1][(nj & 1) * 2]);
        }
        if (it + 2 < 16) { issue(it + 2); cp_commit(); }
    }

#pragma unroll
    for (int mi = 0; mi < 4; mi++) {
        int mrow = m0 + wm * 64 + mi * 16 + gg;
#pragma unroll
        for (int nj = 0; nj < 4; nj++) {
            int col = n0 + wn * 32 + nj * 8 + 2 * tt;
            float* d0 = Cout + (size_t)mrow * DMODEL + col;
            *(float2*)d0 = make_float2(acc[mi][nj][0], acc[mi][nj][1]);
            *(float2*)(d0 + 8 * DMODEL) = make_float2(acc[mi][nj][2], acc[mi][nj][3]);
        }
    }
}

// ---------------------------------------------------------------------------
// den_kernel (fp16 scores): per (64-wide k-stripe kt, bh):
//   S = Q K^T (Q double-buffered), P -> g_Ph fp16 (LOCAL column index);
//   colsums in registers; V stripe (fp16) scaled + transposed into g_Vt.
// ---------------------------------------------------------------------------
__global__ __launch_bounds__(256, 2) void den_kernel() {
    int kt = blockIdx.x;
    int bh = blockIdx.y;

    extern __shared__ float smf[];
    uint32_t sK = smem_u32(smf);                 // fp16 K stripe: 8KB
    uint32_t sQ = sK + 8192;                     // fp16 Q tiles: 2 x 16KB
    float* Vstage = (float*)((char*)smf + 8192 + 32768);  // [64][65] fp32
    __shared__ float colsum[4][64];
    __shared__ float invs[64];

    int t = threadIdx.x, wid = t >> 5;
    int wm = wid & 3, wn = wid >> 2;             // 4x2 warps -> 128q x 64k
    LANE_OFFS();

    const __half* Qg = g_Qh + (size_t)bh * SEQ * DHEAD;
    const __half* Kg = g_Kh + ((size_t)bh * SEQ + kt * 64) * DHEAD;
    __half* Pb = g_Ph + (size_t)bh * SEQ * SEQ + kt * 64;

    auto issueQ = [&](int qt, int s) {
        const __half* src = Qg + (size_t)qt * 128 * DHEAD;
        uint32_t base = sQ + s * 16384;
#pragma unroll
        for (int j = 0; j < 4; j++) {
            int u = t + j * 256;
            int row = u >> 3, ch = u & 7;
            cp16a(base + swz(row * 128 + ch * 16), src + (size_t)row * DHEAD + ch * 8);
        }
    };

#pragma unroll
    for (int j = 0; j < 2; j++) {
        int u = t + j * 256;
        int row = u >> 3, ch = u & 7;
        cp16a(sK + swz(row * 128 + ch * 16), Kg + (size_t)row * DHEAD + ch * 8);
    }
    int qt0 = kt >> 1;
    issueQ(qt0, 0); cp_commit(); cp_wait<0>(); __syncthreads();

    uint32_t aOffU = (uint32_t)(wm * 32 + aRow) * 128 + aK16;
    uint32_t bOffU = (uint32_t)(wn * 32 + bRow) * 128 + bK16;

    float part[4][2];
#pragma unroll
    for (int nj = 0; nj < 4; nj++) { part[nj][0] = 0.0f; part[nj][1] = 0.0f; }

#pragma unroll 1
    for (int qt = qt0; qt < SEQ / 128; qt++) {
        int it = qt - qt0;
        if (qt + 1 < SEQ / 128) { issueQ(qt + 1, (it + 1) & 1); cp_commit(); }

        uint32_t baQ = sQ + (it & 1) * 16384;
        float acc[2][4][4];
#pragma unroll
        for (int mi = 0; mi < 2; mi++)
#pragma unroll
            for (int nj = 0; nj < 4; nj++)
#pragma unroll
                for (int e = 0; e < 4; e++) acc[mi][nj][e] = 0.0f;

#pragma unroll
        for (int slab = 0; slab < 4; slab++) {
            uint32_t a[2][4], b[2][4];
            ldsm4(a[0], baQ + swz(aOffU + slab * 32));
            ldsm4(a[1], baQ + swz(aOffU + 2048 + slab * 32));
            ldsm4(b[0], sK + swz(bOffU + slab * 32));
            ldsm4(b[1], sK + swz(bOffU + 2048 + slab * 32));
#pragma unroll
            for (int mi = 0; mi < 2; mi++)
#pragma unroll
                for (int nj = 0; nj < 4; nj++)
                    mma16h(acc[mi][nj], a[mi], &b[nj >> 1][(nj & 1) * 2]);
        }

        int q0 = qt * 128;
#pragma unroll
        for (int mi = 0; mi < 2; mi++) {
            int row = wm * 32 + mi * 16 + gg;
            int q = q0 + row;
#pragma unroll
            for (int nj = 0; nj < 4; nj++) {
                int kl = wn * 32 + nj * 8 + 2 * tt;
                int kg = kt * 64 + kl;
                float v0 = (kg     <= q) ? __expf((acc[mi][nj][0] + (float)(kg - q)) * SCALE) : 0.0f;
                float v1 = (kg + 1 <= q) ? __expf((acc[mi][nj][1] + (float)(kg + 1 - q)) * SCALE) : 0.0f;
                float v2 = (kg     <= q + 8) ? __expf((acc[mi][nj][2] + (float)(kg - q - 8)) * SCALE) : 0.0f;
                float v3 = (kg + 1 <= q + 8) ? __expf((acc[mi][nj][3] + (float)(kg + 1 - q - 8)) * SCALE) : 0.0f;
                part[nj][0] += v0 + v2;
                part[nj][1] += v1 + v3;
                *(__half2*)&Pb[(size_t)q * SEQ + kl] = __floats2half2_rn(v0, v1);
                *(__half2*)&Pb[(size_t)(q + 8) * SEQ + kl] = __floats2half2_rn(v2, v3);
            }
        }
        cp_wait<0>(); __syncthreads();
    }

#pragma unroll
    for (int nj = 0; nj < 4; nj++)
#pragma unroll
        for (int p = 0; p < 2; p++) {
            float v = part[nj][p];
            v += __shfl_xor_sync(0xffffffffu, v, 4);
            v += __shfl_xor_sync(0xffffffffu, v, 8);
            v += __shfl_xor_sync(0xffffffffu, v, 16);
            part[nj][p] = v;
        }
    if (lane < 4) {
#pragma unroll
        for (int nj = 0; nj < 4; nj++) {
            colsum[wm][wn * 32 + nj * 8 + 2 * lane]     = part[nj][0];
            colsum[wm][wn * 32 + nj * 8 + 2 * lane + 1] = part[nj][1];
        }
    }
    __syncthreads();
    if (t < 64)
        invs[t] = 1.0f / (colsum[0][t] + colsum[1][t] + colsum[2][t] + colsum[3][t]);
    __syncthreads();

    // scale + transpose fp16 V stripe -> g_Vt (staging pitch 65)
    const __half* Vg = g_Vh + ((size_t)bh * SEQ + kt * 64) * DHEAD;
#pragma unroll
    for (int j = 0; j < 2; j++) {
        int u = t + j * 256;                 // 512 x 16B covers 64x64 halves
        int r = u >> 3, e8 = (u & 7) * 8;
        uint4 raw = *(const uint4*)&Vg[(size_t)r * DHEAD + e8];
        float iv = invs[r];
        __half2 h0 = *(__half2*)&raw.x, h1 = *(__half2*)&raw.y;
        __half2 h2 = *(__half2*)&raw.z, h3 = *(__half2*)&raw.w;
        Vstage[r * 65 + e8 + 0] = __low2float(h0) * iv;
        Vstage[r * 65 + e8 + 1] = __high2float(h0) * iv;
        Vstage[r * 65 + e8 + 2] = __low2float(h1) * iv;
        Vstage[r * 65 + e8 + 3] = __high2float(h1) * iv;
        Vstage[r * 65 + e8 + 4] = __low2float(h2) * iv;
        Vstage[r * 65 + e8 + 5] = __high2float(h2) * iv;
        Vstage[r * 65 + e8 + 6] = __low2float(h3) * iv;
        Vstage[r * 65 + e8 + 7] = __high2float(h3) * iv;
    }
    __syncthreads();
    __half* Vt = g_Vt + (size_t)bh * DHEAD * SEQ + kt * 64;
#pragma unroll
    for (int er = 0; er < 8; er++) {
        int e = wid * 8 + er;
#pragma unroll
        for (int half_ = 0; half_ < 2; half_++) {
            int r = lane + half_ * 32;
            Vt[(size_t)e * SEQ + r] = __float2half_rn(Vstage[r * 65 + e]);
        }
    }
}

// ---------------------------------------------------------------------------
// pv_kernel (fp16): Ocat[128q x 64e] = P @ Vt^T, BK=64, 3-stage single-sync.
// ---------------------------------------------------------------------------
__global__ __launch_bounds__(256, 2) void pv_kernel() {
    int qt = (int)gridDim.x - 1 - blockIdx.x;
    int bh = blockIdx.y;
    int b = bh >> 4, h = bh & 15;

    extern __shared__ float smf[];
    uint32_t sP = smem_u32(smf);                 // [3][128 x 128B] = 48KB
    uint32_t sV = sP + 3 * 16384;                // [3][64 x 128B]  = 24KB

    int t = threadIdx.x, wid = t >> 5;
    int wm = wid & 3, wn = wid >> 2;
    LANE_OFFS();

    const __half* Pg = g_Ph + ((size_t)bh * SEQ + qt * 128) * SEQ;
    const __half* Vtg = g_Vt + (size_t)bh * DHEAD * SEQ;

    float acc[2][4][4];
#pragma unroll
    for (int mi = 0; mi < 2; mi++)
#pragma unroll
        for (int nj = 0; nj < 4; nj++)
#pragma unroll
            for (int e = 0; e < 4; e++) acc[mi][nj][e] = 0.0f;

    int niter = 2 * qt + 2;

    auto issue = [&](int it3) {
        int s = it3 % 3;
        uint32_t bP = sP + s * 16384;
#pragma unroll
        for (int j = 0; j < 4; j++) {
            int u = t + j * 256;
            int row = u >> 3, ch = u & 7;
            cp16a(bP + swz(row * 128 + ch * 16), Pg + (size_t)row * SEQ + it3 * 64 + ch * 8);
        }
        uint32_t bV = sV + s * 8192;
#pragma unroll
        for (int j = 0; j < 2; j++) {
            int u = t + j * 256;
            int row = u >> 3, ch = u & 7;
            cp16a(bV + swz(row * 128 + ch * 16), Vtg + (size_t)row * SEQ + it3 * 64 + ch * 8);
        }
    };

    uint32_t aOffU = (uint32_t)(wm * 32 + aRow) * 128 + aK16;
    uint32_t bOffU = (uint32_t)(wn * 32 + bRow) * 128 + bK16;

    issue(0); cp_commit();
    if (niter > 1) { issue(1); cp_commit(); }
#pragma unroll 1
    for (int it = 0; it < niter; it++) {
        if (it + 1 < niter) cp_wait<1>(); else cp_wait<0>();
        __syncthreads();
        uint32_t bP = sP + (it % 3) * 16384;
        uint32_t bV = sV + (it % 3) * 8192;
#pragma unroll
        for (int slab = 0; slab < 4; slab++) {
            uint32_t a[2][4], bfr[2][4];
            ldsm4(a[0], bP + swz(aOffU + slab * 32));
            ldsm4(a[1], bP + swz(aOffU + 2048 + slab * 32));
            ldsm4(bfr[0], bV + swz(bOffU + slab * 32));
            ldsm4(bfr[1], bV + swz(bOffU + 2048 + slab * 32));
#pragma unroll
            for (int mi = 0; mi < 2; mi++)
#pragma unroll
                for (int nj = 0; nj < 4; nj++)
                    mma16h(acc[mi][nj], a[mi], &bfr[nj >> 1][(nj & 1) * 2]);
        }
        if (it + 2 < niter) { issue(it + 2); cp_commit(); }
    }

#pragma unroll
    for (int mi = 0; mi < 2; mi++) {
        int row = qt * 128 + wm * 32 + mi * 16 + gg;
#pragma unroll
        for (int nj = 0; nj < 4; nj++) {
            int colL = wn * 32 + nj * 8 + 2 * tt;
            __half* d0 = g_Ocat + ((size_t)(b * SEQ) + row) * DMODEL + h * 64 + colL;
            *(__half2*)d0 = __floats2half2_rn(acc[mi][nj][0], acc[mi][nj][1]);
            *(__half2*)(d0 + 8 * DMODEL) = __floats2half2_rn(acc[mi][nj][2], acc[mi][nj][3]);
        }
    }
}

// ---------------------------------------------------------------------------
// Launch. Inputs: keys, queries, values, WQ, WK, WV, WO, masking
// ---------------------------------------------------------------------------
extern "C" void kernel_launch(void* const* d_in, const int* in_sizes, int n_in,
                              void* d_out, int out_size) {
    const float* keys    = (const float*)d_in[0];
    const float* queries = (const float*)d_in[1];
    const float* values  = (const float*)d_in[2];
    const float* WQ      = (const float*)d_in[3];
    const float* WK      = (const float*)d_in[4];
    const float* WV      = (const float*)d_in[5];
    const float* WO      = (const float*)d_in[6];
    float* out = (float*)d_out;
    (void)in_sizes; (void)n_in; (void)out_size;

    const int projSmem = 3 * 16384 * 2;                       // 98304
    const int outSmem  = 3 * 16384 * 2;                       // 98304
    const int denSmem  = 8192 + 2 * 16384 + 64 * 65 * 4;      // 57600
    const int pvSmem   = 3 * 16384 + 3 * 8192;                // 73728
    cudaFuncSetAttribute(proj_kernel, cudaFuncAttributeMaxDynamicSharedMemorySize, projSmem);
    cudaFuncSetAttribute(out_kernel,  cudaFuncAttributeMaxDynamicSharedMemorySize, outSmem);
    cudaFuncSetAttribute(den_kernel,  cudaFuncAttributeMaxDynamicSharedMemorySize, denSmem);
    cudaFuncSetAttribute(pv_kernel,   cudaFuncAttributeMaxDynamicSharedMemorySize, pvSmem);

    // prologue (all fp16)
    xprep_kernel<<<dim3(MROWS * DMODEL / 4 / 256, 1, 3), 256>>>(
        (const float4*)queries, (const float4*)keys, (const float4*)values);
    wprep_kernel<<<dim3(DMODEL / 64, NHEAD, 3), 256>>>(WQ, WK, WV);
    woprep_kernel<<<dim3(DMODEL / 64, DMODEL / 64), 256>>>(WO);

    // all projections, uniform fp16 (z=0 Q, z=1 K, z=2 V)
    proj_kernel<<<dim3(MROWS / 128, DMODEL / 128, 3), 256, projSmem>>>();

    // attention (fp16)
    den_kernel<<<dim3(SEQ / 64, BH), 256, denSmem>>>();
    pv_kernel<<<dim3(SEQ / 128, BH), 256, pvSmem>>>();

    // output projection (fp16)
    out_kernel<<<dim3(MROWS / 128, DMODEL / 128), 256, outSmem>>>(out);
}